// round 8
// baseline (speedup 1.0000x reference)
#include <cuda_runtime.h>
#include <cuda_fp16.h>
#include <cstdint>

// Problem constants
#define BB 4096
#define SS 31
#define CC 512
#define HH 8
#define HD 64
#define M_TOT (BB*SS)        // 126976
#define NPOS (SS*SS)         // 961
#define BH (BB*HH)           // 32768
#define EPS 1e-5f
#define INV_SQRT_C 0.044194173824159216f   // 1/sqrt(512)
#define WSCALE 16.0f
#define INV_WSCALE 0.0625f

// ---------------- scratch (static device memory; no allocations) ----------------
__device__ __align__(16) __half g_xh[(size_t)M_TOT * 512];
__device__ __align__(16) __half g_ctxh[(size_t)M_TOT * 512];
__device__ __align__(16) __half g_qh[(size_t)M_TOT * 512];
__device__ __align__(16) __half g_kh[(size_t)M_TOT * 512];
__device__ __align__(16) __half g_vh[(size_t)M_TOT * 512];
// Weights: per row 1024 halves = [512 hi | 512 lo], scaled by 16 (denormal-free lo).
__device__ __align__(16) __half g_wh[(size_t)1536 * 1024];
__device__ __align__(16) __half g_woh[(size_t)512 * 1024];

__device__ __align__(16) float g_energy[(size_t)BH * NPOS];

__device__ __align__(16) float g_ch_sum[CC];
__device__ __align__(16) float g_ch_sq[CC];
__device__ __align__(16) float g_scale[CC];
__device__ __align__(16) float g_shift[CC];
__device__ __align__(16) float g_p_sum[NPOS];
__device__ __align__(16) float g_p_sq[NPOS];
__device__ __align__(16) float g_sc2[NPOS];
__device__ __align__(16) float g_sh2[NPOS];

// ---------------- helpers (family-portable mma/ldmatrix/cp.async) ----------------
__device__ __forceinline__ uint32_t smem_u32(const void* p) {
    uint32_t a;
    asm("{ .reg .u64 t; cvta.to.shared.u64 t, %1; cvt.u32.u64 %0, t; }" : "=r"(a) : "l"(p));
    return a;
}
__device__ __forceinline__ void cp16(uint32_t dst, const void* src) {
    asm volatile("cp.async.cg.shared.global [%0], [%1], 16;" :: "r"(dst), "l"(src) : "memory");
}
__device__ __forceinline__ void cp_commit() {
    asm volatile("cp.async.commit_group;" ::: "memory");
}
__device__ __forceinline__ void cp_wait1() {
    asm volatile("cp.async.wait_group 1;" ::: "memory");
}
__device__ __forceinline__ void cp_wait0() {
    asm volatile("cp.async.wait_group 0;" ::: "memory");
}
__device__ __forceinline__ void ldsm_x4(uint32_t* r, uint32_t addr) {
    asm volatile("ldmatrix.sync.aligned.m8n8.x4.shared.b16 {%0,%1,%2,%3}, [%4];"
                 : "=r"(r[0]), "=r"(r[1]), "=r"(r[2]), "=r"(r[3]) : "r"(addr));
}
__device__ __forceinline__ void mma16816(float* c, const uint32_t* a, const uint32_t* b) {
    asm volatile(
        "mma.sync.aligned.m16n8k16.row.col.f32.f16.f16.f32 "
        "{%0,%1,%2,%3}, {%4,%5,%6,%7}, {%8,%9}, {%0,%1,%2,%3};"
        : "+f"(c[0]), "+f"(c[1]), "+f"(c[2]), "+f"(c[3])
        : "r"(a[0]), "r"(a[1]), "r"(a[2]), "r"(a[3]), "r"(b[0]), "r"(b[1]));
}
#define SWZ(off) ((off) ^ (((off) >> 3) & 0x70u))

// ---------------- kernel: zero reduction buffers ----------------
__global__ void k_zero() {
    int i = threadIdx.x;  // <<<1, 1024>>>
    if (i < CC)   { g_ch_sum[i] = 0.f; g_ch_sq[i] = 0.f; }
    if (i < NPOS) { g_p_sum[i] = 0.f;  g_p_sq[i] = 0.f; }
}

// ---------------- kernel: BN1 channel stats ----------------
__global__ void __launch_bounds__(256) k_bn1_stats(const float* __restrict__ x) {
    const int tid = threadIdx.x;
    const size_t r0 = (size_t)blockIdx.x * 128;
    const float* xp = x + r0 * CC;
    float s0 = 0.f, s1 = 0.f, q0 = 0.f, q1 = 0.f;
    for (int r = 0; r < 128; r++) {
        float v0 = xp[(size_t)r * CC + tid];
        float v1 = xp[(size_t)r * CC + tid + 256];
        s0 += v0; q0 += v0 * v0;
        s1 += v1; q1 += v1 * v1;
    }
    atomicAdd(&g_ch_sum[tid],       s0);
    atomicAdd(&g_ch_sq[tid],        q0);
    atomicAdd(&g_ch_sum[tid + 256], s1);
    atomicAdd(&g_ch_sq[tid + 256],  q1);
}

__global__ void k_bn1_fin(const float* __restrict__ nw, const float* __restrict__ nb) {
    int i = blockIdx.x * blockDim.x + threadIdx.x;  // <<<2,256>>>
    if (i >= CC) return;
    float inv_n = 1.0f / (float)M_TOT;
    float mean = g_ch_sum[i] * inv_n;
    float var  = g_ch_sq[i] * inv_n - mean * mean;
    float rs   = rsqrtf(var + EPS);
    float sc   = rs * nw[i];
    g_scale[i] = sc;
    g_shift[i] = nb[i] - mean * sc;
}

// ---------------- prepass: xn = BN(x) -> fp16 ----------------
__global__ void __launch_bounds__(256) k_split_x(const float* __restrict__ x) {
    size_t t = (size_t)blockIdx.x * 256 + threadIdx.x;  // M_TOT*64 threads, 8 elems each
    size_t m = t >> 6;
    int k = (int)(t & 63) * 8;
    const float* xp = x + m * 512 + k;
    float4 a  = *(const float4*)xp;
    float4 b  = *(const float4*)(xp + 4);
    float4 sA = *(const float4*)(g_scale + k);
    float4 sB = *(const float4*)(g_scale + k + 4);
    float4 hA = *(const float4*)(g_shift + k);
    float4 hB = *(const float4*)(g_shift + k + 4);
    __half hb[8];
    hb[0] = __float2half_rn(fmaf(a.x, sA.x, hA.x));
    hb[1] = __float2half_rn(fmaf(a.y, sA.y, hA.y));
    hb[2] = __float2half_rn(fmaf(a.z, sA.z, hA.z));
    hb[3] = __float2half_rn(fmaf(a.w, sA.w, hA.w));
    hb[4] = __float2half_rn(fmaf(b.x, sB.x, hB.x));
    hb[5] = __float2half_rn(fmaf(b.y, sB.y, hB.y));
    hb[6] = __float2half_rn(fmaf(b.z, sB.z, hB.z));
    hb[7] = __float2half_rn(fmaf(b.w, sB.w, hB.w));
    *(uint4*)(g_xh + m * 512 + k) = *(uint4*)hb;
}

// ---------------- prepass: weights fp16 2-term split, x16 scaled, [512 hi | 512 lo] --
__global__ void __launch_bounds__(256) k_split_w(const float* __restrict__ Wq,
                                                 const float* __restrict__ Wk,
                                                 const float* __restrict__ Wv,
                                                 const float* __restrict__ Wo) {
    int t = blockIdx.x * 256 + threadIdx.x;  // 2048*64 threads
    int row = t >> 6;
    int k = (t & 63) * 8;
    const float* src;
    __half* base;
    if (row < 1536) {
        src = (row < 512) ? (Wq + (size_t)row * 512)
            : (row < 1024) ? (Wk + (size_t)(row - 512) * 512)
                           : (Wv + (size_t)(row - 1024) * 512);
        base = g_wh + (size_t)row * 1024;
    } else {
        src = Wo + (size_t)(row - 1536) * 512;
        base = g_woh + (size_t)(row - 1536) * 1024;
    }
    float4 a = *(const float4*)(src + k);
    float4 b = *(const float4*)(src + k + 4);
    float v[8] = {a.x, a.y, a.z, a.w, b.x, b.y, b.z, b.w};
    __half hi[8], lo[8];
#pragma unroll
    for (int i = 0; i < 8; i++) {
        float sv = v[i] * WSCALE;                    // scale -> lo stays normal in fp16
        hi[i] = __float2half_rn(sv);
        lo[i] = __float2half_rn(sv - __half2float(hi[i]));
    }
    *(uint4*)(base + k)       = *(uint4*)hi;
    *(uint4*)(base + 512 + k) = *(uint4*)lo;
}

// ---------------- HMMA GEMM: CTA 128x128, 4 warps, extended-K fp16 (scaled B) -------
// K_ext = 1024: chunks 0-7 = A(0-7) x B_hi, chunks 8-15 = A(0-7) x B_lo.
// Epilogue de-scales by 1/16.
// MODE 0: A=g_xh, B=g_wh (1536 rows) -> writes g_qh/g_kh/g_vh fp16
// MODE 1: A=g_ctxh, B=g_woh (512 rows) -> out = D/16 + bias + resid (fp32)
template<int MODE>
__global__ void __launch_bounds__(128) k_mma_gemm(const float* __restrict__ bias,
                                                  const float* __restrict__ resid,
                                                  float* __restrict__ Dout) {
    extern __shared__ char sm[];  // 2 stages x (A 16KB + B 16KB) = 64KB
    const int tid = threadIdx.x, lane = tid & 31, w = tid >> 5;
    const int wm = w >> 1, wn = w & 1;
    const int m0 = blockIdx.y * 128, n0g = blockIdx.x * 128;
    const __half* Asrc = (MODE == 0) ? g_xh : g_ctxh;
    const __half* Bsrc = (MODE == 0) ? g_wh : g_woh;
    const uint32_t sbase = smem_u32(sm);

    float c[4][8][4];
#pragma unroll
    for (int i = 0; i < 4; i++)
#pragma unroll
        for (int j = 0; j < 8; j++)
#pragma unroll
            for (int l = 0; l < 4; l++) c[i][j][l] = 0.f;

    const int a_row = lane & 15;
    const int a_cb  = (lane >> 4) * 16;
    const int b_row = (lane & 7) + ((lane >> 4) & 1) * 8;
    const int b_cb  = ((lane >> 3) & 1) * 16;

    auto load_stage = [&](int st, int ch) {
        uint32_t ab = sbase + st * 32768;
        uint32_t bb = ab + 16384;
        const int cha = ch & 7;   // A chunk (reused for hi and lo passes)
#pragma unroll
        for (int j = 0; j < 8; j++) {
            int u = j * 128 + tid, r = u >> 3, q = u & 7;
            cp16(ab + SWZ((uint32_t)(r * 128 + q * 16)),
                 Asrc + (size_t)(m0 + r) * 512 + cha * 64 + q * 8);
        }
#pragma unroll
        for (int j = 0; j < 8; j++) {
            int u = j * 128 + tid, r = u >> 3, q = u & 7;
            cp16(bb + SWZ((uint32_t)(r * 128 + q * 16)),
                 Bsrc + (size_t)(n0g + r) * 1024 + ch * 64 + q * 8);
        }
        cp_commit();
    };

    load_stage(0, 0);

    for (int it = 0; it < 16; it++) {
        if (it + 1 < 16) { load_stage((it + 1) & 1, it + 1); cp_wait1(); }
        else             { cp_wait0(); }
        __syncthreads();

        const uint32_t ab = sbase + (it & 1) * 32768;
        const uint32_t bb = ab + 16384;

#pragma unroll
        for (int ks = 0; ks < 4; ks++) {
            uint32_t a4[4][4], bf[16];
#pragma unroll
            for (int mi = 0; mi < 4; mi++)
                ldsm_x4(a4[mi],
                        ab + SWZ((uint32_t)((wm * 64 + mi * 16 + a_row) * 128 + ks * 32 + a_cb)));
#pragma unroll
            for (int nt = 0; nt < 4; nt++)
                ldsm_x4(&bf[nt * 4],
                        bb + SWZ((uint32_t)((wn * 64 + nt * 16 + b_row) * 128 + ks * 32 + b_cb)));
#pragma unroll
            for (int mi = 0; mi < 4; mi++)
#pragma unroll
                for (int nj = 0; nj < 8; nj++)
                    mma16816(c[mi][nj], a4[mi], &bf[nj * 2]);
        }
        __syncthreads();
    }

    // ---------------- epilogue (de-scale by 1/16) ----------------
    const int r1 = lane >> 2;
    const int c0 = (lane & 3) * 2;
#pragma unroll
    for (int mi = 0; mi < 4; mi++) {
        const int gr = m0 + wm * 64 + mi * 16;
#pragma unroll
        for (int nj = 0; nj < 8; nj++) {
            const int gc = n0g + wn * 64 + nj * 8 + c0;
            if (MODE == 0) {
                const int sel = gc >> 9;
                const int col = gc & 511;
                __half* op = (sel == 0) ? g_qh : ((sel == 1) ? g_kh : g_vh);
                *(__half2*)(op + (size_t)(gr + r1) * 512 + col) =
                    __floats2half2_rn(c[mi][nj][0] * INV_WSCALE, c[mi][nj][1] * INV_WSCALE);
                *(__half2*)(op + (size_t)(gr + r1 + 8) * 512 + col) =
                    __floats2half2_rn(c[mi][nj][2] * INV_WSCALE, c[mi][nj][3] * INV_WSCALE);
            } else {
                const int col = gc;
                const float b0 = bias[col], b1 = bias[col + 1];
                {
                    const size_t off = (size_t)(gr + r1) * 512 + col;
                    float2 rv = *(const float2*)(resid + off);
                    *(float2*)(Dout + off) =
                        make_float2(fmaf(c[mi][nj][0], INV_WSCALE, b0 + rv.x),
                                    fmaf(c[mi][nj][1], INV_WSCALE, b1 + rv.y));
                }
                {
                    const size_t off = (size_t)(gr + r1 + 8) * 512 + col;
                    float2 rv = *(const float2*)(resid + off);
                    *(float2*)(Dout + off) =
                        make_float2(fmaf(c[mi][nj][2], INV_WSCALE, b0 + rv.x),
                                    fmaf(c[mi][nj][3], INV_WSCALE, b1 + rv.y));
                }
            }
        }
    }
}

// ---------------- kernel: energy = q . k per (b,h), vectorized ----------------
__global__ void __launch_bounds__(256) k_energy() {
    const int bh = blockIdx.x;
    const int b = bh >> 3, h = bh & 7;
    __shared__ __align__(16) float sq[SS][65];
    __shared__ __align__(16) float skT[64][36];
    const int tid = threadIdx.x;
    const __half* qp = g_qh + (size_t)(b * SS) * 512 + h * 64;
    const __half* kp = g_kh + (size_t)(b * SS) * 512 + h * 64;
    for (int idx = tid; idx < SS * 64; idx += 256) {
        int s = idx >> 6, d = idx & 63;
        sq[s][d]  = __half2float(qp[(size_t)s * 512 + d]);
        skT[d][s] = __half2float(kp[(size_t)s * 512 + d]);
    }
    if (tid < 64) skT[tid][31] = 0.f;
    __syncthreads();
    if (tid < 248) {
        const int i = tid >> 3, j0 = (tid & 7) * 4;
        float4 acc = make_float4(0.f, 0.f, 0.f, 0.f);
#pragma unroll 8
        for (int d = 0; d < 64; d++) {
            float a = sq[i][d];
            float4 kv = *(float4*)&skT[d][j0];
            acc.x = fmaf(a, kv.x, acc.x);
            acc.y = fmaf(a, kv.y, acc.y);
            acc.z = fmaf(a, kv.z, acc.z);
            acc.w = fmaf(a, kv.w, acc.w);
        }
        float* ep = g_energy + (size_t)bh * NPOS + i * SS + j0;
        ep[0] = acc.x; ep[1] = acc.y; ep[2] = acc.z;
        if (j0 < 28) ep[3] = acc.w;
    }
}

// ---------------- kernel: BN2 position stats over (B,H) ----------------
__global__ void __launch_bounds__(256) k_bn2_stats() {
    const int tid = threadIdx.x;
    const size_t r0 = (size_t)blockIdx.x * 128;
    const float* ep = g_energy + r0 * NPOS;
    float s[4] = {0.f, 0.f, 0.f, 0.f};
    float q[4] = {0.f, 0.f, 0.f, 0.f};
    for (int r = 0; r < 128; r++) {
        const float* row = ep + (size_t)r * NPOS;
#pragma unroll
        for (int j = 0; j < 4; j++) {
            int col = tid + j * 256;
            if (col < NPOS) {
                float v = row[col];
                s[j] += v; q[j] += v * v;
            }
        }
    }
#pragma unroll
    for (int j = 0; j < 4; j++) {
        int col = tid + j * 256;
        if (col < NPOS) {
            atomicAdd(&g_p_sum[col], s[j]);
            atomicAdd(&g_p_sq[col],  q[j]);
        }
    }
}

__global__ void k_bn2_fin(const float* __restrict__ pw, const float* __restrict__ pb) {
    int i = blockIdx.x * blockDim.x + threadIdx.x;  // <<<4,256>>>
    if (i >= NPOS) return;
    float inv_n = 1.0f / (float)BH;
    float mean = g_p_sum[i] * inv_n;
    float var  = g_p_sq[i] * inv_n - mean * mean;
    float rs   = rsqrtf(var + EPS);
    float a    = rs * pw[i] * INV_SQRT_C;
    g_sc2[i] = a;
    g_sh2[i] = pb[i] * INV_SQRT_C - mean * a;
}

// ---------------- kernel: softmax + attn @ v per (b,h); writes fp16 ctx ----------------
__global__ void __launch_bounds__(256) k_attn() {
    const int bh = blockIdx.x;
    const int b = bh >> 3, h = bh & 7;
    __shared__ __align__(16) float se[SS * 33];
    __shared__ __align__(16) float sv[SS * 64];
    const int tid = threadIdx.x;
    const float* ep = g_energy + (size_t)bh * NPOS;
    for (int p = tid; p < NPOS; p += 256) {
        int i = p / SS, j = p % SS;
        se[i * 33 + j] = fmaf(ep[p], g_sc2[p], g_sh2[p]);
    }
    const __half* vp = g_vh + (size_t)(b * SS) * 512 + h * 64;
    for (int idx = tid; idx < SS * 64; idx += 256) {
        int s = idx >> 6, d = idx & 63;
        sv[s * 64 + d] = __half2float(vp[(size_t)s * 512 + d]);
    }
    __syncthreads();
    const int w = tid >> 5, l = tid & 31;
    for (int r = w; r < SS; r += 8) {
        float val = (l < SS) ? se[r * 33 + l] : -1e30f;
        float mx = val;
#pragma unroll
        for (int off = 16; off > 0; off >>= 1)
            mx = fmaxf(mx, __shfl_xor_sync(0xFFFFFFFFu, mx, off));
        float pe = (l < SS) ? __expf(val - mx) : 0.f;
        float sum = pe;
#pragma unroll
        for (int off = 16; off > 0; off >>= 1)
            sum += __shfl_xor_sync(0xFFFFFFFFu, sum, off);
        if (l < SS) se[r * 33 + l] = pe / sum;
    }
    __syncthreads();
    for (int u = tid; u < SS * 16; u += 256) {
        const int i = u >> 4, d0 = (u & 15) * 4;
        float4 acc = make_float4(0.f, 0.f, 0.f, 0.f);
#pragma unroll
        for (int lk = 0; lk < SS; lk++) {
            float p = se[i * 33 + lk];
            float4 vv = *(float4*)&sv[lk * 64 + d0];
            acc.x = fmaf(p, vv.x, acc.x);
            acc.y = fmaf(p, vv.y, acc.y);
            acc.z = fmaf(p, vv.z, acc.z);
            acc.w = fmaf(p, vv.w, acc.w);
        }
        __half hb[4];
        hb[0] = __float2half_rn(acc.x);
        hb[1] = __float2half_rn(acc.y);
        hb[2] = __float2half_rn(acc.z);
        hb[3] = __float2half_rn(acc.w);
        *(uint2*)(g_ctxh + (size_t)(b * SS + i) * 512 + h * 64 + d0) = *(uint2*)hb;
    }
}

// ---------------- launch ----------------
extern "C" void kernel_launch(void* const* d_in, const int* in_sizes, int n_in,
                              void* d_out, int out_size) {
    const float* x     = (const float*)d_in[0];
    const float* nw    = (const float*)d_in[1];
    const float* nbias = (const float*)d_in[2];
    const float* Wq    = (const float*)d_in[3];
    const float* Wk    = (const float*)d_in[4];
    const float* Wv    = (const float*)d_in[5];
    const float* Wout  = (const float*)d_in[6];
    const float* b_out = (const float*)d_in[7];
    const float* pw    = (const float*)d_in[8];
    const float* pb    = (const float*)d_in[9];
    float* out = (float*)d_out;

    cudaFuncSetAttribute(k_mma_gemm<0>, cudaFuncAttributeMaxDynamicSharedMemorySize, 65536);
    cudaFuncSetAttribute(k_mma_gemm<1>, cudaFuncAttributeMaxDynamicSharedMemorySize, 65536);

    k_zero<<<1, 1024>>>();
    k_split_w<<<512, 256>>>(Wq, Wk, Wv, Wout);
    k_bn1_stats<<<M_TOT / 128, 256>>>(x);
    k_bn1_fin<<<2, 256>>>(nw, nbias);
    k_split_x<<<M_TOT / 4, 256>>>(x);

    k_mma_gemm<0><<<dim3(12, 992), 128, 65536>>>(nullptr, nullptr, nullptr);

    k_energy<<<BH, 256>>>();
    k_bn2_stats<<<BH / 128, 256>>>();
    k_bn2_fin<<<4, 256>>>(pw, pb);
    k_attn<<<BH, 256>>>();

    k_mma_gemm<1><<<dim3(4, 992), 128, 65536>>>(b_out, x, out);
}

// round 9
// speedup vs baseline: 1.2223x; 1.2223x over previous
#include <cuda_runtime.h>
#include <cuda_bf16.h>
#include <cstdint>

// Problem constants
#define BB 4096
#define SS 31
#define CC 512
#define HH 8
#define HD 64
#define M_TOT (BB*SS)        // 126976
#define NPOS (SS*SS)         // 961
#define BH (BB*HH)           // 32768
#define EPS 1e-5f
#define INV_SQRT_C 0.044194173824159216f   // 1/sqrt(512)
#define NPART 992            // BN1 partial blocks

// ---------------- scratch (static device memory; no allocations) ----------------
// Packed bf16-split layout: per row of 512, 16 chunks; each chunk = 64 bf16 = [32 hi | 32 lo] (128 B).
__device__ __align__(16) __nv_bfloat16 g_xp[(size_t)M_TOT * 1024];
__device__ __align__(16) __nv_bfloat16 g_ctxp[(size_t)M_TOT * 1024];
__device__ __align__(16) __nv_bfloat16 g_wp[(size_t)1536 * 1024];
__device__ __align__(16) __nv_bfloat16 g_wop[(size_t)512 * 1024];

__device__ __align__(16) float g_q[(size_t)M_TOT * CC];
__device__ __align__(16) float g_k[(size_t)M_TOT * CC];
__device__ __align__(16) float g_v[(size_t)M_TOT * CC];
__device__ __align__(16) float g_energy[(size_t)BH * NPOS];

// BN1 two-phase partials (no atomics)
__device__ __align__(16) float g_psum[(size_t)NPART * CC];
__device__ __align__(16) float g_psq[(size_t)NPART * CC];
__device__ __align__(16) float g_scale[CC];
__device__ __align__(16) float g_shift[CC];
__device__ __align__(16) float g_p_sum[NPOS];
__device__ __align__(16) float g_p_sq[NPOS];
__device__ __align__(16) float g_sc2[NPOS];
__device__ __align__(16) float g_sh2[NPOS];

// ---------------- helpers (family-portable mma/ldmatrix/cp.async) ----------------
__device__ __forceinline__ uint32_t smem_u32(const void* p) {
    uint32_t a;
    asm("{ .reg .u64 t; cvta.to.shared.u64 t, %1; cvt.u32.u64 %0, t; }" : "=r"(a) : "l"(p));
    return a;
}
__device__ __forceinline__ void cp16(uint32_t dst, const void* src) {
    asm volatile("cp.async.cg.shared.global [%0], [%1], 16;" :: "r"(dst), "l"(src) : "memory");
}
__device__ __forceinline__ void cp_commit() {
    asm volatile("cp.async.commit_group;" ::: "memory");
}
__device__ __forceinline__ void cp_wait1() {
    asm volatile("cp.async.wait_group 1;" ::: "memory");
}
__device__ __forceinline__ void cp_wait0() {
    asm volatile("cp.async.wait_group 0;" ::: "memory");
}
__device__ __forceinline__ void ldsm_x4(uint32_t* r, uint32_t addr) {
    asm volatile("ldmatrix.sync.aligned.m8n8.x4.shared.b16 {%0,%1,%2,%3}, [%4];"
                 : "=r"(r[0]), "=r"(r[1]), "=r"(r[2]), "=r"(r[3]) : "r"(addr));
}
__device__ __forceinline__ void mma16816(float* c, const uint32_t* a, const uint32_t* b) {
    asm volatile(
        "mma.sync.aligned.m16n8k16.row.col.f32.bf16.bf16.f32 "
        "{%0,%1,%2,%3}, {%4,%5,%6,%7}, {%8,%9}, {%0,%1,%2,%3};"
        : "+f"(c[0]), "+f"(c[1]), "+f"(c[2]), "+f"(c[3])
        : "r"(a[0]), "r"(a[1]), "r"(a[2]), "r"(a[3]), "r"(b[0]), "r"(b[1]));
}
#define SWZ(off) ((off) ^ (((off) >> 3) & 0x70u))

// ---------------- launch #1: BN1 partial stats + weight split ----------------
// blocks [0, 992): BN1 partials over 128 rows each (no atomics).
// blocks [992, 1504): bf16-split the 2048 weight rows (Wq|Wk|Wv|Wo).
__global__ void __launch_bounds__(256) k_pre1(const float* __restrict__ x,
                                              const float* __restrict__ Wq,
                                              const float* __restrict__ Wk,
                                              const float* __restrict__ Wv,
                                              const float* __restrict__ Wo) {
    const int tid = threadIdx.x;
    const int blk = blockIdx.x;
    if (blk < NPART) {
        const size_t r0 = (size_t)blk * 128;
        const float* xp = x + r0 * CC;
        float s0 = 0.f, s1 = 0.f, q0 = 0.f, q1 = 0.f;
        for (int r = 0; r < 128; r++) {
            float v0 = xp[(size_t)r * CC + tid];
            float v1 = xp[(size_t)r * CC + tid + 256];
            s0 += v0; q0 += v0 * v0;
            s1 += v1; q1 += v1 * v1;
        }
        g_psum[(size_t)blk * CC + tid]       = s0;
        g_psq [(size_t)blk * CC + tid]       = q0;
        g_psum[(size_t)blk * CC + tid + 256] = s1;
        g_psq [(size_t)blk * CC + tid + 256] = q1;
    } else {
        int t = (blk - NPART) * 256 + tid;   // [0, 131072)
        int row = t >> 6;
        int oct = t & 63;
        int c = oct >> 2, pos = (oct & 3) << 3, k = oct << 3;
        const float* src;
        __nv_bfloat16* dst;
        if (row < 1536) {
            src = (row < 512) ? (Wq + (size_t)row * 512)
                : (row < 1024) ? (Wk + (size_t)(row - 512) * 512)
                               : (Wv + (size_t)(row - 1024) * 512);
            dst = g_wp + (((size_t)row * 16 + c) << 6) + pos;
        } else {
            int r2 = row - 1536;
            src = Wo + (size_t)r2 * 512;
            dst = g_wop + (((size_t)r2 * 16 + c) << 6) + pos;
        }
        float4 a = *(const float4*)(src + k);
        float4 b = *(const float4*)(src + k + 4);
        float v[8] = {a.x, a.y, a.z, a.w, b.x, b.y, b.z, b.w};
        __nv_bfloat16 hi[8], lo[8];
#pragma unroll
        for (int i = 0; i < 8; i++) {
            hi[i] = __float2bfloat16(v[i]);
            lo[i] = __float2bfloat16(v[i] - __bfloat162float(hi[i]));
        }
        *(uint4*)dst        = *(uint4*)hi;
        *(uint4*)(dst + 32) = *(uint4*)lo;
    }
}

// ---------------- launch #2: BN1 finalize (reduce partials) + zero BN2 buffers ------
__global__ void __launch_bounds__(256) k_pre2(const float* __restrict__ nw,
                                              const float* __restrict__ nb) {
    const int gid = blockIdx.x * 256 + threadIdx.x;   // <<<4,256>>> -> [0,1024)
    if (gid < CC) {
        float s = 0.f, q = 0.f;
        for (int p = 0; p < NPART; p++) {
            s += g_psum[(size_t)p * CC + gid];
            q += g_psq [(size_t)p * CC + gid];
        }
        const float inv_n = 1.0f / (float)M_TOT;
        float mean = s * inv_n;
        float var  = q * inv_n - mean * mean;
        float rs   = rsqrtf(var + EPS);
        float sc   = rs * nw[gid];
        g_scale[gid] = sc;
        g_shift[gid] = nb[gid] - mean * sc;
    }
    if (gid < NPOS) { g_p_sum[gid] = 0.f; g_p_sq[gid] = 0.f; }
}

// ---------------- launch #3: xn = BN(x), bf16-split, packed ----------------
__global__ void __launch_bounds__(256) k_split_x(const float* __restrict__ x) {
    size_t t = (size_t)blockIdx.x * 256 + threadIdx.x;  // M_TOT*64 threads, 8 elems each
    size_t m = t >> 6;
    int oct = (int)(t & 63);
    int c = oct >> 2, pos = (oct & 3) << 3, k = oct << 3;
    const float* xp = x + m * 512 + k;
    float4 a  = *(const float4*)xp;
    float4 b  = *(const float4*)(xp + 4);
    float4 sA = *(const float4*)(g_scale + k);
    float4 sB = *(const float4*)(g_scale + k + 4);
    float4 hA = *(const float4*)(g_shift + k);
    float4 hB = *(const float4*)(g_shift + k + 4);
    float v[8];
    v[0] = fmaf(a.x, sA.x, hA.x); v[1] = fmaf(a.y, sA.y, hA.y);
    v[2] = fmaf(a.z, sA.z, hA.z); v[3] = fmaf(a.w, sA.w, hA.w);
    v[4] = fmaf(b.x, sB.x, hB.x); v[5] = fmaf(b.y, sB.y, hB.y);
    v[6] = fmaf(b.z, sB.z, hB.z); v[7] = fmaf(b.w, sB.w, hB.w);
    __nv_bfloat16 hi[8], lo[8];
#pragma unroll
    for (int i = 0; i < 8; i++) {
        hi[i] = __float2bfloat16(v[i]);
        lo[i] = __float2bfloat16(v[i] - __bfloat162float(hi[i]));
    }
    __nv_bfloat16* dst = g_xp + ((m * 16 + c) << 6) + pos;
    *(uint4*)dst        = *(uint4*)hi;
    *(uint4*)(dst + 32) = *(uint4*)lo;
}

// ---------------- launch #4: HMMA GEMM (R3 config: 4 warps, 64x64 warp tiles) -------
// CTA 128x128, BK=32 fp32-k per chunk, 3-term bf16 split.
// MODE 0: A = g_xp, B = g_wp (1536 rows) -> writes g_q/g_k/g_v fp32
// MODE 1: A = g_ctxp, B = g_wop (512 rows) -> out = D + bias + resid
template<int MODE>
__global__ void __launch_bounds__(128) k_mma_gemm(const float* __restrict__ bias,
                                                  const float* __restrict__ resid,
                                                  float* __restrict__ Dout) {
    extern __shared__ char sm[];  // 2 stages x (A 16KB + B 16KB) = 64KB
    const int tid = threadIdx.x, lane = tid & 31, w = tid >> 5;
    const int wm = w >> 1, wn = w & 1;
    const int m0 = blockIdx.y * 128, n0g = blockIdx.x * 128;
    const __nv_bfloat16* Asrc = (MODE == 0) ? g_xp : g_ctxp;
    const __nv_bfloat16* Bsrc = (MODE == 0) ? g_wp : g_wop;
    const uint32_t sbase = smem_u32(sm);

    float c[4][8][4];
#pragma unroll
    for (int i = 0; i < 4; i++)
#pragma unroll
        for (int j = 0; j < 8; j++)
#pragma unroll
            for (int l = 0; l < 4; l++) c[i][j][l] = 0.f;

    // lane addressing for ldmatrix
    const int a_row = lane & 15;
    const int a_cb  = (lane >> 4) * 16;
    const int b_row = (lane & 7) + ((lane >> 4) & 1) * 8;
    const int b_cb  = ((lane >> 3) & 1) * 16;

    auto load_stage = [&](int st, int ch) {
        uint32_t abase = sbase + st * 32768;
        uint32_t bbase = abase + 16384;
#pragma unroll
        for (int j = 0; j < 8; j++) {
            int u = j * 128 + tid, r = u >> 3, q = u & 7;
            cp16(abase + SWZ((uint32_t)(r * 128 + q * 16)),
                 Asrc + (((size_t)(m0 + r) * 16 + ch) << 6) + q * 8);
        }
#pragma unroll
        for (int j = 0; j < 8; j++) {
            int u = j * 128 + tid, r = u >> 3, q = u & 7;
            cp16(bbase + SWZ((uint32_t)(r * 128 + q * 16)),
                 Bsrc + (((size_t)(n0g + r) * 16 + ch) << 6) + q * 8);
        }
        cp_commit();
    };

    load_stage(0, 0);

    for (int it = 0; it < 16; it++) {
        if (it + 1 < 16) { load_stage((it + 1) & 1, it + 1); cp_wait1(); }
        else             { cp_wait0(); }
        __syncthreads();

        const uint32_t abase = sbase + (it & 1) * 32768;
        const uint32_t bbase = abase + 16384;

#pragma unroll
        for (int ks = 0; ks < 2; ks++) {
            uint32_t ah[16], al[16], bh[16], bl[16];
#pragma unroll
            for (int mi = 0; mi < 4; mi++)
                ldsm_x4(&ah[mi * 4],
                        abase + SWZ((uint32_t)((wm * 64 + mi * 16 + a_row) * 128 + ks * 32 + a_cb)));
#pragma unroll
            for (int nt = 0; nt < 4; nt++)
                ldsm_x4(&bh[nt * 4],
                        bbase + SWZ((uint32_t)((wn * 64 + nt * 16 + b_row) * 128 + ks * 32 + b_cb)));
            // term 1: hiA x hiB
#pragma unroll
            for (int mi = 0; mi < 4; mi++)
#pragma unroll
                for (int nj = 0; nj < 8; nj++)
                    mma16816(c[mi][nj], &ah[mi * 4], &bh[nj * 2]);
            // lo B
#pragma unroll
            for (int nt = 0; nt < 4; nt++)
                ldsm_x4(&bl[nt * 4],
                        bbase + SWZ((uint32_t)((wn * 64 + nt * 16 + b_row) * 128 + 64 + ks * 32 + b_cb)));
            // term 2: hiA x loB
#pragma unroll
            for (int mi = 0; mi < 4; mi++)
#pragma unroll
                for (int nj = 0; nj < 8; nj++)
                    mma16816(c[mi][nj], &ah[mi * 4], &bl[nj * 2]);
            // lo A
#pragma unroll
            for (int mi = 0; mi < 4; mi++)
                ldsm_x4(&al[mi * 4],
                        abase + SWZ((uint32_t)((wm * 64 + mi * 16 + a_row) * 128 + 64 + ks * 32 + a_cb)));
            // term 3: loA x hiB
#pragma unroll
            for (int mi = 0; mi < 4; mi++)
#pragma unroll
                for (int nj = 0; nj < 8; nj++)
                    mma16816(c[mi][nj], &al[mi * 4], &bh[nj * 2]);
        }
        __syncthreads();
    }

    // ---------------- epilogue: register fragments -> global ----------------
    const int r1 = lane >> 2;
    const int c0 = (lane & 3) * 2;
#pragma unroll
    for (int mi = 0; mi < 4; mi++) {
        const int gr = m0 + wm * 64 + mi * 16;
#pragma unroll
        for (int nj = 0; nj < 8; nj++) {
            const int gc = n0g + wn * 64 + nj * 8 + c0;
            if (MODE == 0) {
                const int sel = gc >> 9;
                const int col = gc & 511;
                float* op = (sel == 0) ? g_q : ((sel == 1) ? g_k : g_v);
                *(float2*)(op + (size_t)(gr + r1) * 512 + col) =
                    make_float2(c[mi][nj][0], c[mi][nj][1]);
                *(float2*)(op + (size_t)(gr + r1 + 8) * 512 + col) =
                    make_float2(c[mi][nj][2], c[mi][nj][3]);
            } else {
                const int col = gc;
                const float b0 = bias[col], b1 = bias[col + 1];
                {
                    const size_t off = (size_t)(gr + r1) * 512 + col;
                    float2 rv = *(const float2*)(resid + off);
                    *(float2*)(Dout + off) =
                        make_float2(c[mi][nj][0] + b0 + rv.x, c[mi][nj][1] + b1 + rv.y);
                }
                {
                    const size_t off = (size_t)(gr + r1 + 8) * 512 + col;
                    float2 rv = *(const float2*)(resid + off);
                    *(float2*)(Dout + off) =
                        make_float2(c[mi][nj][2] + b0 + rv.x, c[mi][nj][3] + b1 + rv.y);
                }
            }
        }
    }
}

// ---------------- kernel: energy = q . k per (b,h) ----------------
__global__ void __launch_bounds__(256) k_energy() {
    const int bh = blockIdx.x;
    const int b = bh >> 3, h = bh & 7;
    __shared__ float sq[SS * 65];
    __shared__ float sk[SS * 65];
    const int tid = threadIdx.x;
    const float* qp = g_q + (size_t)(b * SS) * CC + h * HD;
    const float* kp = g_k + (size_t)(b * SS) * CC + h * HD;
    for (int idx = tid; idx < SS * HD; idx += 256) {
        int s = idx / HD, d = idx % HD;
        sq[s * 65 + d] = qp[(size_t)s * CC + d];
        sk[s * 65 + d] = kp[(size_t)s * CC + d];
    }
    __syncthreads();
    float* ep = g_energy + (size_t)bh * NPOS;
    for (int p = tid; p < NPOS; p += 256) {
        int i = p / SS, j = p % SS;
        float accv = 0.f;
#pragma unroll
        for (int d = 0; d < HD; d++) accv += sq[i * 65 + d] * sk[j * 65 + d];
        ep[p] = accv;
    }
}

// ---------------- kernel: BN2 position stats over (B,H) ----------------
__global__ void __launch_bounds__(256) k_bn2_stats() {
    const int tid = threadIdx.x;
    const size_t r0 = (size_t)blockIdx.x * 128;
    const float* ep = g_energy + r0 * NPOS;
    float s[4] = {0.f, 0.f, 0.f, 0.f};
    float q[4] = {0.f, 0.f, 0.f, 0.f};
    for (int r = 0; r < 128; r++) {
        const float* row = ep + (size_t)r * NPOS;
#pragma unroll
        for (int j = 0; j < 4; j++) {
            int col = tid + j * 256;
            if (col < NPOS) {
                float v = row[col];
                s[j] += v; q[j] += v * v;
            }
        }
    }
#pragma unroll
    for (int j = 0; j < 4; j++) {
        int col = tid + j * 256;
        if (col < NPOS) {
            atomicAdd(&g_p_sum[col], s[j]);
            atomicAdd(&g_p_sq[col],  q[j]);
        }
    }
}

__global__ void k_bn2_fin(const float* __restrict__ pw, const float* __restrict__ pb) {
    int i = blockIdx.x * blockDim.x + threadIdx.x;  // <<<4,256>>>
    if (i >= NPOS) return;
    float inv_n = 1.0f / (float)BH;
    float mean = g_p_sum[i] * inv_n;
    float var  = g_p_sq[i] * inv_n - mean * mean;
    float rs   = rsqrtf(var + EPS);
    float a    = rs * pw[i] * INV_SQRT_C;
    g_sc2[i] = a;
    g_sh2[i] = pb[i] * INV_SQRT_C - mean * a;
}

// ---------------- kernel: softmax + attn @ v per (b,h); writes split ctx ----------------
__global__ void __launch_bounds__(256) k_attn() {
    const int bh = blockIdx.x;
    const int b = bh >> 3, h = bh & 7;
    __shared__ float se[SS * 32];
    __shared__ float sv[SS * HD];
    const int tid = threadIdx.x;
    const float* ep = g_energy + (size_t)bh * NPOS;
    for (int p = tid; p < NPOS; p += 256) {
        int i = p / SS, j = p % SS;
        se[i * 32 + j] = fmaf(ep[p], g_sc2[p], g_sh2[p]);
    }
    const float* vp = g_v + (size_t)(b * SS) * CC + h * HD;
    for (int idx = tid; idx < SS * HD; idx += 256) {
        int s = idx / HD, d = idx % HD;
        sv[s * HD + d] = vp[(size_t)s * CC + d];
    }
    __syncthreads();
    const int w = tid >> 5, l = tid & 31;
    for (int r = w; r < SS; r += 8) {
        float val = (l < SS) ? se[r * 32 + l] : -1e30f;
        float mx = val;
#pragma unroll
        for (int off = 16; off > 0; off >>= 1)
            mx = fmaxf(mx, __shfl_xor_sync(0xFFFFFFFFu, mx, off));
        float pe = (l < SS) ? __expf(val - mx) : 0.f;
        float sum = pe;
#pragma unroll
        for (int off = 16; off > 0; off >>= 1)
            sum += __shfl_xor_sync(0xFFFFFFFFu, sum, off);
        if (l < SS) se[r * 32 + l] = pe / sum;
    }
    __syncthreads();
    for (int idx = tid; idx < SS * HD; idx += 256) {
        int i = idx / HD, d = idx % HD;
        float accv = 0.f;
#pragma unroll
        for (int lk = 0; lk < SS; lk++) accv += se[i * 32 + lk] * sv[lk * HD + d];
        __nv_bfloat16 hi = __float2bfloat16(accv);
        __nv_bfloat16 lo = __float2bfloat16(accv - __bfloat162float(hi));
        int colg = h * HD + d;
        int c = colg >> 5, pos = colg & 31;
        size_t base = (((size_t)(b * SS + i) * 16 + c) << 6) + pos;
        g_ctxp[base]      = hi;
        g_ctxp[base + 32] = lo;
    }
}

// ---------------- launch ----------------
extern "C" void kernel_launch(void* const* d_in, const int* in_sizes, int n_in,
                              void* d_out, int out_size) {
    const float* x     = (const float*)d_in[0];
    const float* nw    = (const float*)d_in[1];
    const float* nbias = (const float*)d_in[2];
    const float* Wq    = (const float*)d_in[3];
    const float* Wk    = (const float*)d_in[4];
    const float* Wv    = (const float*)d_in[5];
    const float* Wout  = (const float*)d_in[6];
    const float* b_out = (const float*)d_in[7];
    const float* pw    = (const float*)d_in[8];
    const float* pb    = (const float*)d_in[9];
    float* out = (float*)d_out;

    cudaFuncSetAttribute(k_mma_gemm<0>, cudaFuncAttributeMaxDynamicSharedMemorySize, 65536);
    cudaFuncSetAttribute(k_mma_gemm<1>, cudaFuncAttributeMaxDynamicSharedMemorySize, 65536);

    k_pre1<<<NPART + 512, 256>>>(x, Wq, Wk, Wv, Wout);       // #1
    k_pre2<<<4, 256>>>(nw, nbias);                           // #2
    k_split_x<<<M_TOT / 4, 256>>>(x);                        // #3
    k_mma_gemm<0><<<dim3(12, 992), 128, 65536>>>(nullptr, nullptr, nullptr);  // #4 <- ncu

    k_energy<<<BH, 256>>>();                                 // #5
    k_bn2_stats<<<BH / 128, 256>>>();                        // #6
    k_bn2_fin<<<4, 256>>>(pw, pb);                           // #7
    k_attn<<<BH, 256>>>();                                   // #8
    k_mma_gemm<1><<<dim3(4, 992), 128, 65536>>>(b_out, x, out);  // #9
}

// round 10
// speedup vs baseline: 1.4448x; 1.1821x over previous
#include <cuda_runtime.h>
#include <cuda_bf16.h>
#include <cuda_fp16.h>
#include <cstdint>

// Problem constants
#define BB 4096
#define SS 31
#define CC 512
#define HH 8
#define HD 64
#define M_TOT (BB*SS)        // 126976
#define NPOS (SS*SS)         // 961
#define BH (BB*HH)           // 32768
#define EPS 1e-5f
#define INV_SQRT_C 0.044194173824159216f   // 1/sqrt(512)
#define NPART 992            // BN1 partial blocks

// ---------------- scratch (static device memory; no allocations) ----------------
// Packed bf16-split layout: per row of 512, 16 chunks; each chunk = 64 bf16 = [32 hi | 32 lo] (128 B).
__device__ __align__(16) __nv_bfloat16 g_xp[(size_t)M_TOT * 1024];
__device__ __align__(16) __nv_bfloat16 g_ctxp[(size_t)M_TOT * 1024];
__device__ __align__(16) __nv_bfloat16 g_wp[(size_t)1536 * 1024];
__device__ __align__(16) __nv_bfloat16 g_wop[(size_t)512 * 1024];

__device__ __align__(16) __half g_qh[(size_t)M_TOT * CC];
__device__ __align__(16) __half g_kh[(size_t)M_TOT * CC];
__device__ __align__(16) __half g_vh[(size_t)M_TOT * CC];
__device__ __align__(16) float g_energy[(size_t)BH * NPOS];

// BN1 two-phase partials (no atomics)
__device__ __align__(16) float g_psum[(size_t)NPART * CC];
__device__ __align__(16) float g_psq[(size_t)NPART * CC];
__device__ __align__(16) float g_scale[CC];
__device__ __align__(16) float g_shift[CC];
__device__ __align__(16) float g_p_sum[NPOS];
__device__ __align__(16) float g_p_sq[NPOS];
__device__ __align__(16) float g_sc2[NPOS];
__device__ __align__(16) float g_sh2[NPOS];

// ---------------- helpers (family-portable mma/ldmatrix/cp.async) ----------------
__device__ __forceinline__ uint32_t smem_u32(const void* p) {
    uint32_t a;
    asm("{ .reg .u64 t; cvta.to.shared.u64 t, %1; cvt.u32.u64 %0, t; }" : "=r"(a) : "l"(p));
    return a;
}
__device__ __forceinline__ void cp16(uint32_t dst, const void* src) {
    asm volatile("cp.async.cg.shared.global [%0], [%1], 16;" :: "r"(dst), "l"(src) : "memory");
}
__device__ __forceinline__ void cp_commit() {
    asm volatile("cp.async.commit_group;" ::: "memory");
}
__device__ __forceinline__ void cp_wait1() {
    asm volatile("cp.async.wait_group 1;" ::: "memory");
}
__device__ __forceinline__ void cp_wait0() {
    asm volatile("cp.async.wait_group 0;" ::: "memory");
}
__device__ __forceinline__ void ldsm_x4(uint32_t* r, uint32_t addr) {
    asm volatile("ldmatrix.sync.aligned.m8n8.x4.shared.b16 {%0,%1,%2,%3}, [%4];"
                 : "=r"(r[0]), "=r"(r[1]), "=r"(r[2]), "=r"(r[3]) : "r"(addr));
}
__device__ __forceinline__ void mma16816(float* c, const uint32_t* a, const uint32_t* b) {
    asm volatile(
        "mma.sync.aligned.m16n8k16.row.col.f32.bf16.bf16.f32 "
        "{%0,%1,%2,%3}, {%4,%5,%6,%7}, {%8,%9}, {%0,%1,%2,%3};"
        : "+f"(c[0]), "+f"(c[1]), "+f"(c[2]), "+f"(c[3])
        : "r"(a[0]), "r"(a[1]), "r"(a[2]), "r"(a[3]), "r"(b[0]), "r"(b[1]));
}
__device__ __forceinline__ void mma16816h(float* c, const uint32_t* a, const uint32_t* b) {
    asm volatile(
        "mma.sync.aligned.m16n8k16.row.col.f32.f16.f16.f32 "
        "{%0,%1,%2,%3}, {%4,%5,%6,%7}, {%8,%9}, {%0,%1,%2,%3};"
        : "+f"(c[0]), "+f"(c[1]), "+f"(c[2]), "+f"(c[3])
        : "r"(a[0]), "r"(a[1]), "r"(a[2]), "r"(a[3]), "r"(b[0]), "r"(b[1]));
}
#define SWZ(off) ((off) ^ (((off) >> 3) & 0x70u))

// ---------------- launch #1: BN1 partial stats + weight split ----------------
__global__ void __launch_bounds__(256) k_pre1(const float* __restrict__ x,
                                              const float* __restrict__ Wq,
                                              const float* __restrict__ Wk,
                                              const float* __restrict__ Wv,
                                              const float* __restrict__ Wo) {
    const int tid = threadIdx.x;
    const int blk = blockIdx.x;
    if (blk < NPART) {
        const size_t r0 = (size_t)blk * 128;
        const float* xp = x + r0 * CC;
        float s0 = 0.f, s1 = 0.f, q0 = 0.f, q1 = 0.f;
        for (int r = 0; r < 128; r++) {
            float v0 = xp[(size_t)r * CC + tid];
            float v1 = xp[(size_t)r * CC + tid + 256];
            s0 += v0; q0 += v0 * v0;
            s1 += v1; q1 += v1 * v1;
        }
        g_psum[(size_t)blk * CC + tid]       = s0;
        g_psq [(size_t)blk * CC + tid]       = q0;
        g_psum[(size_t)blk * CC + tid + 256] = s1;
        g_psq [(size_t)blk * CC + tid + 256] = q1;
    } else {
        int t = (blk - NPART) * 256 + tid;   // [0, 131072)
        int row = t >> 6;
        int oct = t & 63;
        int c = oct >> 2, pos = (oct & 3) << 3, k = oct << 3;
        const float* src;
        __nv_bfloat16* dst;
        if (row < 1536) {
            src = (row < 512) ? (Wq + (size_t)row * 512)
                : (row < 1024) ? (Wk + (size_t)(row - 512) * 512)
                               : (Wv + (size_t)(row - 1024) * 512);
            dst = g_wp + (((size_t)row * 16 + c) << 6) + pos;
        } else {
            int r2 = row - 1536;
            src = Wo + (size_t)r2 * 512;
            dst = g_wop + (((size_t)r2 * 16 + c) << 6) + pos;
        }
        float4 a = *(const float4*)(src + k);
        float4 b = *(const float4*)(src + k + 4);
        float v[8] = {a.x, a.y, a.z, a.w, b.x, b.y, b.z, b.w};
        __nv_bfloat16 hi[8], lo[8];
#pragma unroll
        for (int i = 0; i < 8; i++) {
            hi[i] = __float2bfloat16(v[i]);
            lo[i] = __float2bfloat16(v[i] - __bfloat162float(hi[i]));
        }
        *(uint4*)dst        = *(uint4*)hi;
        *(uint4*)(dst + 32) = *(uint4*)lo;
    }
}

// ---------------- launch #2: BN1 finalize + zero BN2 buffers ----------------
__global__ void __launch_bounds__(256) k_pre2(const float* __restrict__ nw,
                                              const float* __restrict__ nb) {
    const int gid = blockIdx.x * 256 + threadIdx.x;   // <<<4,256>>> -> [0,1024)
    if (gid < CC) {
        float s = 0.f, q = 0.f;
        for (int p = 0; p < NPART; p++) {
            s += g_psum[(size_t)p * CC + gid];
            q += g_psq [(size_t)p * CC + gid];
        }
        const float inv_n = 1.0f / (float)M_TOT;
        float mean = s * inv_n;
        float var  = q * inv_n - mean * mean;
        float rs   = rsqrtf(var + EPS);
        float sc   = rs * nw[gid];
        g_scale[gid] = sc;
        g_shift[gid] = nb[gid] - mean * sc;
    }
    if (gid < NPOS) { g_p_sum[gid] = 0.f; g_p_sq[gid] = 0.f; }
}

// ---------------- launch #3: xn = BN(x), bf16-split, packed ----------------
__global__ void __launch_bounds__(256) k_split_x(const float* __restrict__ x) {
    size_t t = (size_t)blockIdx.x * 256 + threadIdx.x;  // M_TOT*64 threads, 8 elems each
    size_t m = t >> 6;
    int oct = (int)(t & 63);
    int c = oct >> 2, pos = (oct & 3) << 3, k = oct << 3;
    const float* xp = x + m * 512 + k;
    float4 a  = *(const float4*)xp;
    float4 b  = *(const float4*)(xp + 4);
    float4 sA = *(const float4*)(g_scale + k);
    float4 sB = *(const float4*)(g_scale + k + 4);
    float4 hA = *(const float4*)(g_shift + k);
    float4 hB = *(const float4*)(g_shift + k + 4);
    float v[8];
    v[0] = fmaf(a.x, sA.x, hA.x); v[1] = fmaf(a.y, sA.y, hA.y);
    v[2] = fmaf(a.z, sA.z, hA.z); v[3] = fmaf(a.w, sA.w, hA.w);
    v[4] = fmaf(b.x, sB.x, hB.x); v[5] = fmaf(b.y, sB.y, hB.y);
    v[6] = fmaf(b.z, sB.z, hB.z); v[7] = fmaf(b.w, sB.w, hB.w);
    __nv_bfloat16 hi[8], lo[8];
#pragma unroll
    for (int i = 0; i < 8; i++) {
        hi[i] = __float2bfloat16(v[i]);
        lo[i] = __float2bfloat16(v[i] - __bfloat162float(hi[i]));
    }
    __nv_bfloat16* dst = g_xp + ((m * 16 + c) << 6) + pos;
    *(uint4*)dst        = *(uint4*)hi;
    *(uint4*)(dst + 32) = *(uint4*)lo;
}

// ---------------- launch #4: HMMA GEMM (4 warps, 64x64 warp tiles, 3-term bf16) -----
// MODE 0: A = g_xp, B = g_wp (1536 rows) -> writes g_qh/g_kh/g_vh fp16
// MODE 1: A = g_ctxp, B = g_wop (512 rows) -> out = D + bias + resid (fp32)
template<int MODE>
__global__ void __launch_bounds__(128) k_mma_gemm(const float* __restrict__ bias,
                                                  const float* __restrict__ resid,
                                                  float* __restrict__ Dout) {
    extern __shared__ char sm[];  // 2 stages x (A 16KB + B 16KB) = 64KB
    const int tid = threadIdx.x, lane = tid & 31, w = tid >> 5;
    const int wm = w >> 1, wn = w & 1;
    const int m0 = blockIdx.y * 128, n0g = blockIdx.x * 128;
    const __nv_bfloat16* Asrc = (MODE == 0) ? g_xp : g_ctxp;
    const __nv_bfloat16* Bsrc = (MODE == 0) ? g_wp : g_wop;
    const uint32_t sbase = smem_u32(sm);

    float c[4][8][4];
#pragma unroll
    for (int i = 0; i < 4; i++)
#pragma unroll
        for (int j = 0; j < 8; j++)
#pragma unroll
            for (int l = 0; l < 4; l++) c[i][j][l] = 0.f;

    const int a_row = lane & 15;
    const int a_cb  = (lane >> 4) * 16;
    const int b_row = (lane & 7) + ((lane >> 4) & 1) * 8;
    const int b_cb  = ((lane >> 3) & 1) * 16;

    auto load_stage = [&](int st, int ch) {
        uint32_t abase = sbase + st * 32768;
        uint32_t bbase = abase + 16384;
#pragma unroll
        for (int j = 0; j < 8; j++) {
            int u = j * 128 + tid, r = u >> 3, q = u & 7;
            cp16(abase + SWZ((uint32_t)(r * 128 + q * 16)),
                 Asrc + (((size_t)(m0 + r) * 16 + ch) << 6) + q * 8);
        }
#pragma unroll
        for (int j = 0; j < 8; j++) {
            int u = j * 128 + tid, r = u >> 3, q = u & 7;
            cp16(bbase + SWZ((uint32_t)(r * 128 + q * 16)),
                 Bsrc + (((size_t)(n0g + r) * 16 + ch) << 6) + q * 8);
        }
        cp_commit();
    };

    load_stage(0, 0);

    for (int it = 0; it < 16; it++) {
        if (it + 1 < 16) { load_stage((it + 1) & 1, it + 1); cp_wait1(); }
        else             { cp_wait0(); }
        __syncthreads();

        const uint32_t abase = sbase + (it & 1) * 32768;
        const uint32_t bbase = abase + 16384;

#pragma unroll
        for (int ks = 0; ks < 2; ks++) {
            uint32_t ah[16], al[16], bh[16], bl[16];
#pragma unroll
            for (int mi = 0; mi < 4; mi++)
                ldsm_x4(&ah[mi * 4],
                        abase + SWZ((uint32_t)((wm * 64 + mi * 16 + a_row) * 128 + ks * 32 + a_cb)));
#pragma unroll
            for (int nt = 0; nt < 4; nt++)
                ldsm_x4(&bh[nt * 4],
                        bbase + SWZ((uint32_t)((wn * 64 + nt * 16 + b_row) * 128 + ks * 32 + b_cb)));
#pragma unroll
            for (int mi = 0; mi < 4; mi++)
#pragma unroll
                for (int nj = 0; nj < 8; nj++)
                    mma16816(c[mi][nj], &ah[mi * 4], &bh[nj * 2]);
#pragma unroll
            for (int nt = 0; nt < 4; nt++)
                ldsm_x4(&bl[nt * 4],
                        bbase + SWZ((uint32_t)((wn * 64 + nt * 16 + b_row) * 128 + 64 + ks * 32 + b_cb)));
#pragma unroll
            for (int mi = 0; mi < 4; mi++)
#pragma unroll
                for (int nj = 0; nj < 8; nj++)
                    mma16816(c[mi][nj], &ah[mi * 4], &bl[nj * 2]);
#pragma unroll
            for (int mi = 0; mi < 4; mi++)
                ldsm_x4(&al[mi * 4],
                        abase + SWZ((uint32_t)((wm * 64 + mi * 16 + a_row) * 128 + 64 + ks * 32 + a_cb)));
#pragma unroll
            for (int mi = 0; mi < 4; mi++)
#pragma unroll
                for (int nj = 0; nj < 8; nj++)
                    mma16816(c[mi][nj], &al[mi * 4], &bh[nj * 2]);
        }
        __syncthreads();
    }

    // ---------------- epilogue ----------------
    const int r1 = lane >> 2;
    const int c0 = (lane & 3) * 2;
#pragma unroll
    for (int mi = 0; mi < 4; mi++) {
        const int gr = m0 + wm * 64 + mi * 16;
#pragma unroll
        for (int nj = 0; nj < 8; nj++) {
            const int gc = n0g + wn * 64 + nj * 8 + c0;
            if (MODE == 0) {
                const int sel = gc >> 9;
                const int col = gc & 511;
                __half* op = (sel == 0) ? g_qh : ((sel == 1) ? g_kh : g_vh);
                *(__half2*)(op + (size_t)(gr + r1) * 512 + col) =
                    __floats2half2_rn(c[mi][nj][0], c[mi][nj][1]);
                *(__half2*)(op + (size_t)(gr + r1 + 8) * 512 + col) =
                    __floats2half2_rn(c[mi][nj][2], c[mi][nj][3]);
            } else {
                const int col = gc;
                const float b0 = bias[col], b1 = bias[col + 1];
                {
                    const size_t off = (size_t)(gr + r1) * 512 + col;
                    float2 rv = *(const float2*)(resid + off);
                    *(float2*)(Dout + off) =
                        make_float2(c[mi][nj][0] + b0 + rv.x, c[mi][nj][1] + b1 + rv.y);
                }
                {
                    const size_t off = (size_t)(gr + r1 + 8) * 512 + col;
                    float2 rv = *(const float2*)(resid + off);
                    *(float2*)(Dout + off) =
                        make_float2(c[mi][nj][2] + b0 + rv.x, c[mi][nj][3] + b1 + rv.y);
                }
            }
        }
    }
}

// ---------------- launch #5: energy via MMA + fused BN2 partials ----------------
// block = one batch element b; 8 warps = 8 heads. q,k tiles 32x64 fp16, row stride
// 144B (conflict-free ldmatrix). Energy staged in smem, written coalesced; per-block
// BN2 partials reduced over heads and atomically added.
#define ET_ROWB 144
#define ET_SZ  (32 * ET_ROWB)          // 4608 B per head tile
#define E_SMEM (16 * ET_SZ)            // q tiles [8] + k tiles [8] = 73728 B

__global__ void __launch_bounds__(256) k_energy_mma() {
    extern __shared__ char sm[];
    const int tid = threadIdx.x, lane = tid & 31, w = tid >> 5;   // w = head
    const int b = blockIdx.x;
    const uint32_t sbase = smem_u32(sm);
    const uint32_t qt = sbase + w * ET_SZ;
    const uint32_t kt = sbase + 8 * ET_SZ + w * ET_SZ;

    const __half* qsrc = g_qh + (size_t)(b * SS) * 512 + w * 64;
    const __half* ksrc = g_kh + (size_t)(b * SS) * 512 + w * 64;
    // fill rows 0..30 (31 rows x 8 chunks of 16B)
    for (int i = lane; i < 248; i += 32) {
        int row = i >> 3, q8 = i & 7;
        cp16(qt + row * ET_ROWB + q8 * 16, qsrc + (size_t)row * 512 + q8 * 8);
        cp16(kt + row * ET_ROWB + q8 * 16, ksrc + (size_t)row * 512 + q8 * 8);
    }
    cp_commit();
    cp_wait0();
    // zero row 31 of both tiles
    if (lane < 16) {
        uint32_t base = (lane < 8) ? qt : kt;
        int q8 = lane & 7;
        uint4 z = make_uint4(0u, 0u, 0u, 0u);
        *(uint4*)(sm + (base - sbase) + 31 * ET_ROWB + q8 * 16) = z;
    }
    __syncthreads();

    float c[2][4][4];
#pragma unroll
    for (int i = 0; i < 2; i++)
#pragma unroll
        for (int j = 0; j < 4; j++)
#pragma unroll
            for (int l = 0; l < 4; l++) c[i][j][l] = 0.f;

    const int a_row = lane & 15;
    const int a_cb  = (lane >> 4) * 16;
    const int b_row = (lane & 7) + ((lane >> 4) & 1) * 8;
    const int b_cb  = ((lane >> 3) & 1) * 16;

#pragma unroll
    for (int ks = 0; ks < 4; ks++) {
        uint32_t af[2][4], bf[8];
#pragma unroll
        for (int mi = 0; mi < 2; mi++)
            ldsm_x4(af[mi], qt + (mi * 16 + a_row) * ET_ROWB + ks * 32 + a_cb);
#pragma unroll
        for (int g = 0; g < 2; g++)
            ldsm_x4(&bf[g * 4], kt + (g * 16 + b_row) * ET_ROWB + ks * 32 + b_cb);
#pragma unroll
        for (int mi = 0; mi < 2; mi++)
#pragma unroll
            for (int nj = 0; nj < 4; nj++)
                mma16816h(c[mi][nj], af[mi], &bf[nj * 2]);
    }
    __syncthreads();   // tiles dead; reuse smem as staging

    float* stage = (float*)sm;   // [8][32*32]
    const int r0 = lane >> 2, c0 = (lane & 3) * 2;
#pragma unroll
    for (int mi = 0; mi < 2; mi++)
#pragma unroll
        for (int nj = 0; nj < 4; nj++) {
            int rr = mi * 16 + r0, cc = nj * 8 + c0;
            stage[w * 1024 + rr * 32 + cc]           = c[mi][nj][0];
            stage[w * 1024 + rr * 32 + cc + 1]       = c[mi][nj][1];
            stage[w * 1024 + (rr + 8) * 32 + cc]     = c[mi][nj][2];
            stage[w * 1024 + (rr + 8) * 32 + cc + 1] = c[mi][nj][3];
        }
    __syncthreads();

    float* ebase = g_energy + (size_t)(b * 8) * NPOS;
    for (int p = tid; p < NPOS; p += 256) {
        int r = p / SS, cph = p - r * SS;
        int idx = r * 32 + cph;
        float s = 0.f, q = 0.f;
#pragma unroll
        for (int h = 0; h < 8; h++) {
            float v = stage[h * 1024 + idx];
            ebase[(size_t)h * NPOS + p] = v;
            s += v; q += v * v;
        }
        atomicAdd(&g_p_sum[p], s);
        atomicAdd(&g_p_sq[p],  q);
    }
}

// ---------------- launch #6: BN2 finalize ----------------
__global__ void k_bn2_fin(const float* __restrict__ pw, const float* __restrict__ pb) {
    int i = blockIdx.x * blockDim.x + threadIdx.x;  // <<<4,256>>>
    if (i >= NPOS) return;
    float inv_n = 1.0f / (float)BH;
    float mean = g_p_sum[i] * inv_n;
    float var  = g_p_sq[i] * inv_n - mean * mean;
    float rs   = rsqrtf(var + EPS);
    float a    = rs * pw[i] * INV_SQRT_C;
    g_sc2[i] = a;
    g_sh2[i] = pb[i] * INV_SQRT_C - mean * a;
}

// ---------------- launch #7: softmax + attn @ v per (b,h); writes split ctx ---------
__global__ void __launch_bounds__(256) k_attn() {
    const int bh = blockIdx.x;
    const int b = bh >> 3, h = bh & 7;
    __shared__ float se[SS * 32];
    __shared__ float sv[SS * HD];
    const int tid = threadIdx.x;
    const float* ep = g_energy + (size_t)bh * NPOS;
    for (int p = tid; p < NPOS; p += 256) {
        int i = p / SS, j = p % SS;
        se[i * 32 + j] = fmaf(ep[p], g_sc2[p], g_sh2[p]);
    }
    const __half* vp = g_vh + (size_t)(b * SS) * 512 + h * HD;
    for (int idx = tid; idx < SS * HD; idx += 256) {
        int s = idx / HD, d = idx % HD;
        sv[s * HD + d] = __half2float(vp[(size_t)s * 512 + d]);
    }
    __syncthreads();
    const int w = tid >> 5, l = tid & 31;
    for (int r = w; r < SS; r += 8) {
        float val = (l < SS) ? se[r * 32 + l] : -1e30f;
        float mx = val;
#pragma unroll
        for (int off = 16; off > 0; off >>= 1)
            mx = fmaxf(mx, __shfl_xor_sync(0xFFFFFFFFu, mx, off));
        float pe = (l < SS) ? __expf(val - mx) : 0.f;
        float sum = pe;
#pragma unroll
        for (int off = 16; off > 0; off >>= 1)
            sum += __shfl_xor_sync(0xFFFFFFFFu, sum, off);
        if (l < SS) se[r * 32 + l] = pe / sum;
    }
    __syncthreads();
    for (int idx = tid; idx < SS * HD; idx += 256) {
        int i = idx / HD, d = idx % HD;
        float accv = 0.f;
#pragma unroll
        for (int lk = 0; lk < SS; lk++) accv += se[i * 32 + lk] * sv[lk * HD + d];
        __nv_bfloat16 hi = __float2bfloat16(accv);
        __nv_bfloat16 lo = __float2bfloat16(accv - __bfloat162float(hi));
        int colg = h * HD + d;
        int c = colg >> 5, pos = colg & 31;
        size_t base = (((size_t)(b * SS + i) * 16 + c) << 6) + pos;
        g_ctxp[base]      = hi;
        g_ctxp[base + 32] = lo;
    }
}

// ---------------- launch ----------------
extern "C" void kernel_launch(void* const* d_in, const int* in_sizes, int n_in,
                              void* d_out, int out_size) {
    const float* x     = (const float*)d_in[0];
    const float* nw    = (const float*)d_in[1];
    const float* nbias = (const float*)d_in[2];
    const float* Wq    = (const float*)d_in[3];
    const float* Wk    = (const float*)d_in[4];
    const float* Wv    = (const float*)d_in[5];
    const float* Wout  = (const float*)d_in[6];
    const float* b_out = (const float*)d_in[7];
    const float* pw    = (const float*)d_in[8];
    const float* pb    = (const float*)d_in[9];
    float* out = (float*)d_out;

    cudaFuncSetAttribute(k_mma_gemm<0>, cudaFuncAttributeMaxDynamicSharedMemorySize, 65536);
    cudaFuncSetAttribute(k_mma_gemm<1>, cudaFuncAttributeMaxDynamicSharedMemorySize, 65536);
    cudaFuncSetAttribute(k_energy_mma, cudaFuncAttributeMaxDynamicSharedMemorySize, E_SMEM);

    k_pre1<<<NPART + 512, 256>>>(x, Wq, Wk, Wv, Wout);       // #1
    k_pre2<<<4, 256>>>(nw, nbias);                           // #2
    k_split_x<<<M_TOT / 4, 256>>>(x);                        // #3
    k_mma_gemm<0><<<dim3(12, 992), 128, 65536>>>(nullptr, nullptr, nullptr);  // #4 <- ncu

    k_energy_mma<<<BB, 256, E_SMEM>>>();                     // #5
    k_bn2_fin<<<4, 256>>>(pw, pb);                           // #6
    k_attn<<<BH, 256>>>();                                   // #7
    k_mma_gemm<1><<<dim3(4, 992), 128, 65536>>>(b_out, x, out);  // #8
}

// round 11
// speedup vs baseline: 1.5413x; 1.0668x over previous
#include <cuda_runtime.h>
#include <cuda_bf16.h>
#include <cstdint>

// Problem constants
#define BB 4096
#define SS 31
#define CC 512
#define HH 8
#define HD 64
#define M_TOT (BB*SS)        // 126976
#define NPOS (SS*SS)         // 961
#define BH (BB*HH)           // 32768
#define EPS 1e-5f
#define INV_SQRT_C 0.044194173824159216f   // 1/sqrt(512)
#define NPART 992            // BN1 partial blocks

// ---------------- scratch (static device memory; no allocations) ----------------
// Packed bf16-split layout: per row of 512, 16 chunks; each chunk = 64 bf16 = [32 hi | 32 lo] (128 B).
__device__ __align__(16) __nv_bfloat16 g_xp[(size_t)M_TOT * 1024];
__device__ __align__(16) __nv_bfloat16 g_ctxp[(size_t)M_TOT * 1024];
__device__ __align__(16) __nv_bfloat16 g_wp[(size_t)1536 * 1024];
__device__ __align__(16) __nv_bfloat16 g_wop[(size_t)512 * 1024];

__device__ __align__(16) __nv_bfloat16 g_qb[(size_t)M_TOT * CC];
__device__ __align__(16) __nv_bfloat16 g_kb[(size_t)M_TOT * CC];
__device__ __align__(16) __nv_bfloat16 g_vb[(size_t)M_TOT * CC];
__device__ __align__(16) float g_energy[(size_t)BH * NPOS];

// BN1 two-phase partials (no atomics)
__device__ __align__(16) float g_psum[(size_t)NPART * CC];
__device__ __align__(16) float g_psq[(size_t)NPART * CC];
__device__ __align__(16) float g_scale[CC];
__device__ __align__(16) float g_shift[CC];
__device__ __align__(16) float g_p_sum[NPOS];
__device__ __align__(16) float g_p_sq[NPOS];
__device__ __align__(16) float g_sc2[NPOS];
__device__ __align__(16) float g_sh2[NPOS];

// ---------------- helpers (family-portable mma/ldmatrix/cp.async) ----------------
__device__ __forceinline__ uint32_t smem_u32(const void* p) {
    uint32_t a;
    asm("{ .reg .u64 t; cvta.to.shared.u64 t, %1; cvt.u32.u64 %0, t; }" : "=r"(a) : "l"(p));
    return a;
}
__device__ __forceinline__ void cp16(uint32_t dst, const void* src) {
    asm volatile("cp.async.cg.shared.global [%0], [%1], 16;" :: "r"(dst), "l"(src) : "memory");
}
__device__ __forceinline__ void cp_commit() {
    asm volatile("cp.async.commit_group;" ::: "memory");
}
__device__ __forceinline__ void cp_wait1() {
    asm volatile("cp.async.wait_group 1;" ::: "memory");
}
__device__ __forceinline__ void cp_wait0() {
    asm volatile("cp.async.wait_group 0;" ::: "memory");
}
__device__ __forceinline__ void ldsm_x4(uint32_t* r, uint32_t addr) {
    asm volatile("ldmatrix.sync.aligned.m8n8.x4.shared.b16 {%0,%1,%2,%3}, [%4];"
                 : "=r"(r[0]), "=r"(r[1]), "=r"(r[2]), "=r"(r[3]) : "r"(addr));
}
__device__ __forceinline__ void mma16816(float* c, const uint32_t* a, const uint32_t* b) {
    asm volatile(
        "mma.sync.aligned.m16n8k16.row.col.f32.bf16.bf16.f32 "
        "{%0,%1,%2,%3}, {%4,%5,%6,%7}, {%8,%9}, {%0,%1,%2,%3};"
        : "+f"(c[0]), "+f"(c[1]), "+f"(c[2]), "+f"(c[3])
        : "r"(a[0]), "r"(a[1]), "r"(a[2]), "r"(a[3]), "r"(b[0]), "r"(b[1]));
}
#define SWZ(off) ((off) ^ (((off) >> 3) & 0x70u))

// ---------------- launch #1: BN1 partial stats + weight split ----------------
__global__ void __launch_bounds__(256) k_pre1(const float* __restrict__ x,
                                              const float* __restrict__ Wq,
                                              const float* __restrict__ Wk,
                                              const float* __restrict__ Wv,
                                              const float* __restrict__ Wo) {
    const int tid = threadIdx.x;
    const int blk = blockIdx.x;
    if (blk < NPART) {
        const size_t r0 = (size_t)blk * 128;
        const float* xp = x + r0 * CC;
        float s0 = 0.f, s1 = 0.f, q0 = 0.f, q1 = 0.f;
        for (int r = 0; r < 128; r++) {
            float v0 = xp[(size_t)r * CC + tid];
            float v1 = xp[(size_t)r * CC + tid + 256];
            s0 += v0; q0 += v0 * v0;
            s1 += v1; q1 += v1 * v1;
        }
        g_psum[(size_t)blk * CC + tid]       = s0;
        g_psq [(size_t)blk * CC + tid]       = q0;
        g_psum[(size_t)blk * CC + tid + 256] = s1;
        g_psq [(size_t)blk * CC + tid + 256] = q1;
    } else {
        int t = (blk - NPART) * 256 + tid;   // [0, 131072)
        int row = t >> 6;
        int oct = t & 63;
        int c = oct >> 2, pos = (oct & 3) << 3, k = oct << 3;
        const float* src;
        __nv_bfloat16* dst;
        if (row < 1536) {
            src = (row < 512) ? (Wq + (size_t)row * 512)
                : (row < 1024) ? (Wk + (size_t)(row - 512) * 512)
                               : (Wv + (size_t)(row - 1024) * 512);
            dst = g_wp + (((size_t)row * 16 + c) << 6) + pos;
        } else {
            int r2 = row - 1536;
            src = Wo + (size_t)r2 * 512;
            dst = g_wop + (((size_t)r2 * 16 + c) << 6) + pos;
        }
        float4 a = *(const float4*)(src + k);
        float4 b = *(const float4*)(src + k + 4);
        float v[8] = {a.x, a.y, a.z, a.w, b.x, b.y, b.z, b.w};
        __nv_bfloat16 hi[8], lo[8];
#pragma unroll
        for (int i = 0; i < 8; i++) {
            hi[i] = __float2bfloat16(v[i]);
            lo[i] = __float2bfloat16(v[i] - __bfloat162float(hi[i]));
        }
        *(uint4*)dst        = *(uint4*)hi;
        *(uint4*)(dst + 32) = *(uint4*)lo;
    }
}

// ---------------- launch #2: BN1 finalize + zero BN2 buffers ----------------
__global__ void __launch_bounds__(256) k_pre2(const float* __restrict__ nw,
                                              const float* __restrict__ nb) {
    const int gid = blockIdx.x * 256 + threadIdx.x;   // <<<4,256>>> -> [0,1024)
    if (gid < CC) {
        float s = 0.f, q = 0.f;
        for (int p = 0; p < NPART; p++) {
            s += g_psum[(size_t)p * CC + gid];
            q += g_psq [(size_t)p * CC + gid];
        }
        const float inv_n = 1.0f / (float)M_TOT;
        float mean = s * inv_n;
        float var  = q * inv_n - mean * mean;
        float rs   = rsqrtf(var + EPS);
        float sc   = rs * nw[gid];
        g_scale[gid] = sc;
        g_shift[gid] = nb[gid] - mean * sc;
    }
    if (gid < NPOS) { g_p_sum[gid] = 0.f; g_p_sq[gid] = 0.f; }
}

// ---------------- launch #3: xn = BN(x), bf16-split, packed ----------------
__global__ void __launch_bounds__(256) k_split_x(const float* __restrict__ x) {
    size_t t = (size_t)blockIdx.x * 256 + threadIdx.x;  // M_TOT*64 threads, 8 elems each
    size_t m = t >> 6;
    int oct = (int)(t & 63);
    int c = oct >> 2, pos = (oct & 3) << 3, k = oct << 3;
    const float* xp = x + m * 512 + k;
    float4 a  = *(const float4*)xp;
    float4 b  = *(const float4*)(xp + 4);
    float4 sA = *(const float4*)(g_scale + k);
    float4 sB = *(const float4*)(g_scale + k + 4);
    float4 hA = *(const float4*)(g_shift + k);
    float4 hB = *(const float4*)(g_shift + k + 4);
    float v[8];
    v[0] = fmaf(a.x, sA.x, hA.x); v[1] = fmaf(a.y, sA.y, hA.y);
    v[2] = fmaf(a.z, sA.z, hA.z); v[3] = fmaf(a.w, sA.w, hA.w);
    v[4] = fmaf(b.x, sB.x, hB.x); v[5] = fmaf(b.y, sB.y, hB.y);
    v[6] = fmaf(b.z, sB.z, hB.z); v[7] = fmaf(b.w, sB.w, hB.w);
    __nv_bfloat16 hi[8], lo[8];
#pragma unroll
    for (int i = 0; i < 8; i++) {
        hi[i] = __float2bfloat16(v[i]);
        lo[i] = __float2bfloat16(v[i] - __bfloat162float(hi[i]));
    }
    __nv_bfloat16* dst = g_xp + ((m * 16 + c) << 6) + pos;
    *(uint4*)dst        = *(uint4*)hi;
    *(uint4*)(dst + 32) = *(uint4*)lo;
}

// ---------------- launch #4: HMMA GEMM (4 warps, 64x64 warp tiles, 3-term bf16) -----
// MODE 0: A = g_xp, B = g_wp (1536 rows) -> writes g_qb/g_kb/g_vb bf16
// MODE 1: A = g_ctxp, B = g_wop (512 rows) -> out = D + bias + resid (fp32)
template<int MODE>
__global__ void __launch_bounds__(128) k_mma_gemm(const float* __restrict__ bias,
                                                  const float* __restrict__ resid,
                                                  float* __restrict__ Dout) {
    extern __shared__ char sm[];  // 2 stages x (A 16KB + B 16KB) = 64KB
    const int tid = threadIdx.x, lane = tid & 31, w = tid >> 5;
    const int wm = w >> 1, wn = w & 1;
    const int m0 = blockIdx.y * 128, n0g = blockIdx.x * 128;
    const __nv_bfloat16* Asrc = (MODE == 0) ? g_xp : g_ctxp;
    const __nv_bfloat16* Bsrc = (MODE == 0) ? g_wp : g_wop;
    const uint32_t sbase = smem_u32(sm);

    float c[4][8][4];
#pragma unroll
    for (int i = 0; i < 4; i++)
#pragma unroll
        for (int j = 0; j < 8; j++)
#pragma unroll
            for (int l = 0; l < 4; l++) c[i][j][l] = 0.f;

    const int a_row = lane & 15;
    const int a_cb  = (lane >> 4) * 16;
    const int b_row = (lane & 7) + ((lane >> 4) & 1) * 8;
    const int b_cb  = ((lane >> 3) & 1) * 16;

    auto load_stage = [&](int st, int ch) {
        uint32_t abase = sbase + st * 32768;
        uint32_t bbase = abase + 16384;
#pragma unroll
        for (int j = 0; j < 8; j++) {
            int u = j * 128 + tid, r = u >> 3, q = u & 7;
            cp16(abase + SWZ((uint32_t)(r * 128 + q * 16)),
                 Asrc + (((size_t)(m0 + r) * 16 + ch) << 6) + q * 8);
        }
#pragma unroll
        for (int j = 0; j < 8; j++) {
            int u = j * 128 + tid, r = u >> 3, q = u & 7;
            cp16(bbase + SWZ((uint32_t)(r * 128 + q * 16)),
                 Bsrc + (((size_t)(n0g + r) * 16 + ch) << 6) + q * 8);
        }
        cp_commit();
    };

    load_stage(0, 0);

    for (int it = 0; it < 16; it++) {
        if (it + 1 < 16) { load_stage((it + 1) & 1, it + 1); cp_wait1(); }
        else             { cp_wait0(); }
        __syncthreads();

        const uint32_t abase = sbase + (it & 1) * 32768;
        const uint32_t bbase = abase + 16384;

#pragma unroll
        for (int ks = 0; ks < 2; ks++) {
            uint32_t ah[16], al[16], bh[16], bl[16];
#pragma unroll
            for (int mi = 0; mi < 4; mi++)
                ldsm_x4(&ah[mi * 4],
                        abase + SWZ((uint32_t)((wm * 64 + mi * 16 + a_row) * 128 + ks * 32 + a_cb)));
#pragma unroll
            for (int nt = 0; nt < 4; nt++)
                ldsm_x4(&bh[nt * 4],
                        bbase + SWZ((uint32_t)((wn * 64 + nt * 16 + b_row) * 128 + ks * 32 + b_cb)));
#pragma unroll
            for (int mi = 0; mi < 4; mi++)
#pragma unroll
                for (int nj = 0; nj < 8; nj++)
                    mma16816(c[mi][nj], &ah[mi * 4], &bh[nj * 2]);
#pragma unroll
            for (int nt = 0; nt < 4; nt++)
                ldsm_x4(&bl[nt * 4],
                        bbase + SWZ((uint32_t)((wn * 64 + nt * 16 + b_row) * 128 + 64 + ks * 32 + b_cb)));
#pragma unroll
            for (int mi = 0; mi < 4; mi++)
#pragma unroll
                for (int nj = 0; nj < 8; nj++)
                    mma16816(c[mi][nj], &ah[mi * 4], &bl[nj * 2]);
#pragma unroll
            for (int mi = 0; mi < 4; mi++)
                ldsm_x4(&al[mi * 4],
                        abase + SWZ((uint32_t)((wm * 64 + mi * 16 + a_row) * 128 + 64 + ks * 32 + a_cb)));
#pragma unroll
            for (int mi = 0; mi < 4; mi++)
#pragma unroll
                for (int nj = 0; nj < 8; nj++)
                    mma16816(c[mi][nj], &al[mi * 4], &bh[nj * 2]);
        }
        __syncthreads();
    }

    // ---------------- epilogue ----------------
    const int r1 = lane >> 2;
    const int c0 = (lane & 3) * 2;
#pragma unroll
    for (int mi = 0; mi < 4; mi++) {
        const int gr = m0 + wm * 64 + mi * 16;
#pragma unroll
        for (int nj = 0; nj < 8; nj++) {
            const int gc = n0g + wn * 64 + nj * 8 + c0;
            if (MODE == 0) {
                const int sel = gc >> 9;
                const int col = gc & 511;
                __nv_bfloat16* op = (sel == 0) ? g_qb : ((sel == 1) ? g_kb : g_vb);
                *(__nv_bfloat162*)(op + (size_t)(gr + r1) * 512 + col) =
                    __floats2bfloat162_rn(c[mi][nj][0], c[mi][nj][1]);
                *(__nv_bfloat162*)(op + (size_t)(gr + r1 + 8) * 512 + col) =
                    __floats2bfloat162_rn(c[mi][nj][2], c[mi][nj][3]);
            } else {
                const int col = gc;
                const float b0 = bias[col], b1 = bias[col + 1];
                {
                    const size_t off = (size_t)(gr + r1) * 512 + col;
                    float2 rv = *(const float2*)(resid + off);
                    *(float2*)(Dout + off) =
                        make_float2(c[mi][nj][0] + b0 + rv.x, c[mi][nj][1] + b1 + rv.y);
                }
                {
                    const size_t off = (size_t)(gr + r1 + 8) * 512 + col;
                    float2 rv = *(const float2*)(resid + off);
                    *(float2*)(Dout + off) =
                        make_float2(c[mi][nj][2] + b0 + rv.x, c[mi][nj][3] + b1 + rv.y);
                }
            }
        }
    }
}

// ---------------- launch #5: energy via bf16 MMA + fused BN2 partials ----------------
#define ET_ROWB 144
#define ET_SZ  (32 * ET_ROWB)          // 4608 B per head tile
#define E_SMEM (16 * ET_SZ)            // q tiles [8] + k tiles [8] = 73728 B

__global__ void __launch_bounds__(256) k_energy_mma() {
    extern __shared__ char sm[];
    const int tid = threadIdx.x, lane = tid & 31, w = tid >> 5;   // w = head
    const int b = blockIdx.x;
    const uint32_t sbase = smem_u32(sm);
    const uint32_t qt = sbase + w * ET_SZ;
    const uint32_t kt = sbase + 8 * ET_SZ + w * ET_SZ;

    const __nv_bfloat16* qsrc = g_qb + (size_t)(b * SS) * 512 + w * 64;
    const __nv_bfloat16* ksrc = g_kb + (size_t)(b * SS) * 512 + w * 64;
    for (int i = lane; i < 248; i += 32) {
        int row = i >> 3, q8 = i & 7;
        cp16(qt + row * ET_ROWB + q8 * 16, qsrc + (size_t)row * 512 + q8 * 8);
        cp16(kt + row * ET_ROWB + q8 * 16, ksrc + (size_t)row * 512 + q8 * 8);
    }
    cp_commit();
    cp_wait0();
    if (lane < 16) {
        uint32_t base = (lane < 8) ? qt : kt;
        int q8 = lane & 7;
        uint4 z = make_uint4(0u, 0u, 0u, 0u);
        *(uint4*)(sm + (base - sbase) + 31 * ET_ROWB + q8 * 16) = z;
    }
    __syncthreads();

    float c[2][4][4];
#pragma unroll
    for (int i = 0; i < 2; i++)
#pragma unroll
        for (int j = 0; j < 4; j++)
#pragma unroll
            for (int l = 0; l < 4; l++) c[i][j][l] = 0.f;

    const int a_row = lane & 15;
    const int a_cb  = (lane >> 4) * 16;
    const int b_row = (lane & 7) + ((lane >> 4) & 1) * 8;
    const int b_cb  = ((lane >> 3) & 1) * 16;

#pragma unroll
    for (int ks = 0; ks < 4; ks++) {
        uint32_t af[2][4], bf[8];
#pragma unroll
        for (int mi = 0; mi < 2; mi++)
            ldsm_x4(af[mi], qt + (mi * 16 + a_row) * ET_ROWB + ks * 32 + a_cb);
#pragma unroll
        for (int g = 0; g < 2; g++)
            ldsm_x4(&bf[g * 4], kt + (g * 16 + b_row) * ET_ROWB + ks * 32 + b_cb);
#pragma unroll
        for (int mi = 0; mi < 2; mi++)
#pragma unroll
            for (int nj = 0; nj < 4; nj++)
                mma16816(c[mi][nj], af[mi], &bf[nj * 2]);
    }
    __syncthreads();   // tiles dead; reuse smem as staging

    float* stage = (float*)sm;   // [8][32*32]
    const int r0 = lane >> 2, c0 = (lane & 3) * 2;
#pragma unroll
    for (int mi = 0; mi < 2; mi++)
#pragma unroll
        for (int nj = 0; nj < 4; nj++) {
            int rr = mi * 16 + r0, cc = nj * 8 + c0;
            stage[w * 1024 + rr * 32 + cc]           = c[mi][nj][0];
            stage[w * 1024 + rr * 32 + cc + 1]       = c[mi][nj][1];
            stage[w * 1024 + (rr + 8) * 32 + cc]     = c[mi][nj][2];
            stage[w * 1024 + (rr + 8) * 32 + cc + 1] = c[mi][nj][3];
        }
    __syncthreads();

    float* ebase = g_energy + (size_t)(b * 8) * NPOS;
    for (int p = tid; p < NPOS; p += 256) {
        int r = p / SS, cph = p - r * SS;
        int idx = r * 32 + cph;
        float s = 0.f, q = 0.f;
#pragma unroll
        for (int h = 0; h < 8; h++) {
            float v = stage[h * 1024 + idx];
            ebase[(size_t)h * NPOS + p] = v;
            s += v; q += v * v;
        }
        atomicAdd(&g_p_sum[p], s);
        atomicAdd(&g_p_sq[p],  q);
    }
}

// ---------------- launch #6: BN2 finalize ----------------
__global__ void k_bn2_fin(const float* __restrict__ pw, const float* __restrict__ pb) {
    int i = blockIdx.x * blockDim.x + threadIdx.x;  // <<<4,256>>>
    if (i >= NPOS) return;
    float inv_n = 1.0f / (float)BH;
    float mean = g_p_sum[i] * inv_n;
    float var  = g_p_sq[i] * inv_n - mean * mean;
    float rs   = rsqrtf(var + EPS);
    float a    = rs * pw[i] * INV_SQRT_C;
    g_sc2[i] = a;
    g_sh2[i] = pb[i] * INV_SQRT_C - mean * a;
}

// ---------------- launch #7: softmax + AV via bf16 MMA; writes split ctx -------------
// Block = (batch b, head-half): 128 threads, warp = head. All tiles warp-private
// (only __syncwarp). P split 2-term bf16, V transposed in smem (single bf16).
// smem: [0,16384) float e[4][31][33]; [16384,26624) P_hi [4][32x80B];
//       [26624,36864) P_lo; [36864,57344) V^T [4][64x80B].
#define AT_SMEM 57344

__global__ void __launch_bounds__(128) k_attn_mma() {
    extern __shared__ char smA[];
    const int tid = threadIdx.x, lane = tid & 31, w = tid >> 5;
    const int b = blockIdx.x >> 1;
    const int h = ((blockIdx.x & 1) << 2) + w;
    const uint32_t sbase = smem_u32(smA);
    char* e_t   = smA + w * 4096;
    char* phi_p = smA + 16384 + w * 2560;
    char* plo_p = smA + 26624 + w * 2560;
    char* vt_p  = smA + 36864 + w * 5120;
    const uint32_t phi = sbase + 16384 + w * 2560;
    const uint32_t plo = sbase + 26624 + w * 2560;
    const uint32_t vt  = sbase + 36864 + w * 5120;

    // zero P tiles (covers row 31 / col 31 padding)
    for (int i = lane; i < 640; i += 32) {
        ((uint32_t*)phi_p)[i] = 0u;
        ((uint32_t*)plo_p)[i] = 0u;
    }
    // zero V^T col 31 (k padding)
    for (int d = lane; d < 64; d += 32)
        *(__nv_bfloat16*)(vt_p + d * 80 + 62) = __float2bfloat16(0.f);

    // load energy + BN2 affine into float tile
    const float* ep = g_energy + (size_t)(b * 8 + h) * NPOS;
    for (int p = lane; p < NPOS; p += 32) {
        float v = fmaf(ep[p], g_sc2[p], g_sh2[p]);
        int r = p / SS, cc = p - r * SS;
        ((float*)e_t)[r * 33 + cc] = v;
    }
    // load V slice (31x64) transposed into vt (64 rows x 31 cols)
    const __nv_bfloat16* vp = g_vb + (size_t)(b * SS) * 512 + h * 64;
    for (int i = lane; i < SS * 16; i += 32) {
        int s = i >> 4, d0 = (i & 15) << 2;
        __nv_bfloat16 tmp[4];
        *(uint2*)tmp = *(const uint2*)(vp + (size_t)s * 512 + d0);
#pragma unroll
        for (int j = 0; j < 4; j++)
            *(__nv_bfloat16*)(vt_p + (d0 + j) * 80 + s * 2) = tmp[j];
    }
    __syncwarp();

    // softmax: lane = row (0..30)
    if (lane < SS) {
        float* row = (float*)e_t + lane * 33;
        float mx = -1e30f;
#pragma unroll
        for (int cc = 0; cc < SS; cc++) mx = fmaxf(mx, row[cc]);
        float sum = 0.f;
#pragma unroll
        for (int cc = 0; cc < SS; cc++) {
            float t = __expf(row[cc] - mx);
            row[cc] = t; sum += t;
        }
        float inv = 1.0f / sum;
#pragma unroll
        for (int cc = 0; cc < SS; cc++) {
            float p = row[cc] * inv;
            __nv_bfloat16 hi = __float2bfloat16(p);
            __nv_bfloat16 lo = __float2bfloat16(p - __bfloat162float(hi));
            *(__nv_bfloat16*)(phi_p + lane * 80 + cc * 2) = hi;
            *(__nv_bfloat16*)(plo_p + lane * 80 + cc * 2) = lo;
        }
    }
    __syncwarp();

    // MMA: ctx[32x64] = P[32x32] @ V^T'[64x32]  (2-term P split)
    float acc[2][8][4];
#pragma unroll
    for (int i = 0; i < 2; i++)
#pragma unroll
        for (int j = 0; j < 8; j++)
#pragma unroll
            for (int l = 0; l < 4; l++) acc[i][j][l] = 0.f;

    const int a_row = lane & 15;
    const int a_cb  = (lane >> 4) * 16;
    const int b_row = (lane & 7) + ((lane >> 4) & 1) * 8;
    const int b_cb  = ((lane >> 3) & 1) * 16;

#pragma unroll
    for (int ks = 0; ks < 2; ks++) {
        uint32_t pf[2][4], lf[2][4], bfr[16];
#pragma unroll
        for (int mi = 0; mi < 2; mi++) {
            ldsm_x4(pf[mi], phi + (mi * 16 + a_row) * 80 + ks * 32 + a_cb);
            ldsm_x4(lf[mi], plo + (mi * 16 + a_row) * 80 + ks * 32 + a_cb);
        }
#pragma unroll
        for (int nt = 0; nt < 4; nt++)
            ldsm_x4(&bfr[nt * 4], vt + (nt * 16 + b_row) * 80 + ks * 32 + b_cb);
#pragma unroll
        for (int mi = 0; mi < 2; mi++)
#pragma unroll
            for (int nj = 0; nj < 8; nj++)
                mma16816(acc[mi][nj], pf[mi], &bfr[nj * 2]);
#pragma unroll
        for (int mi = 0; mi < 2; mi++)
#pragma unroll
            for (int nj = 0; nj < 8; nj++)
                mma16816(acc[mi][nj], lf[mi], &bfr[nj * 2]);
    }

    // epilogue: write packed bf16-split ctx
    const int r1 = lane >> 2, c0 = (lane & 3) * 2;
#pragma unroll
    for (int mi = 0; mi < 2; mi++) {
#pragma unroll
        for (int nj = 0; nj < 8; nj++) {
            const int d = nj * 8 + c0;
            const int colg = h * 64 + d;
            const int chunk = colg >> 5, pos = colg & 31;
            const int q1 = mi * 16 + r1;        // 0..7 / 16..23 (<31 always)
            const int q2 = q1 + 8;              // 8..15 / 24..31
            {
                float v0 = acc[mi][nj][0], v1 = acc[mi][nj][1];
                __nv_bfloat16 h0 = __float2bfloat16(v0), h1 = __float2bfloat16(v1);
                __nv_bfloat162 hh; hh.x = h0; hh.y = h1;
                __nv_bfloat162 ll;
                ll.x = __float2bfloat16(v0 - __bfloat162float(h0));
                ll.y = __float2bfloat16(v1 - __bfloat162float(h1));
                size_t base = ((((size_t)b * 31 + q1) * 16 + chunk) << 6) + pos;
                *(__nv_bfloat162*)(g_ctxp + base)      = hh;
                *(__nv_bfloat162*)(g_ctxp + base + 32) = ll;
            }
            if (q2 < 31) {
                float v0 = acc[mi][nj][2], v1 = acc[mi][nj][3];
                __nv_bfloat16 h0 = __float2bfloat16(v0), h1 = __float2bfloat16(v1);
                __nv_bfloat162 hh; hh.x = h0; hh.y = h1;
                __nv_bfloat162 ll;
                ll.x = __float2bfloat16(v0 - __bfloat162float(h0));
                ll.y = __float2bfloat16(v1 - __bfloat162float(h1));
                size_t base = ((((size_t)b * 31 + q2) * 16 + chunk) << 6) + pos;
                *(__nv_bfloat162*)(g_ctxp + base)      = hh;
                *(__nv_bfloat162*)(g_ctxp + base + 32) = ll;
            }
        }
    }
}

// ---------------- launch ----------------
extern "C" void kernel_launch(void* const* d_in, const int* in_sizes, int n_in,
                              void* d_out, int out_size) {
    const float* x     = (const float*)d_in[0];
    const float* nw    = (const float*)d_in[1];
    const float* nbias = (const float*)d_in[2];
    const float* Wq    = (const float*)d_in[3];
    const float* Wk    = (const float*)d_in[4];
    const float* Wv    = (const float*)d_in[5];
    const float* Wout  = (const float*)d_in[6];
    const float* b_out = (const float*)d_in[7];
    const float* pw    = (const float*)d_in[8];
    const float* pb    = (const float*)d_in[9];
    float* out = (float*)d_out;

    cudaFuncSetAttribute(k_mma_gemm<0>, cudaFuncAttributeMaxDynamicSharedMemorySize, 65536);
    cudaFuncSetAttribute(k_mma_gemm<1>, cudaFuncAttributeMaxDynamicSharedMemorySize, 65536);
    cudaFuncSetAttribute(k_energy_mma, cudaFuncAttributeMaxDynamicSharedMemorySize, E_SMEM);
    cudaFuncSetAttribute(k_attn_mma, cudaFuncAttributeMaxDynamicSharedMemorySize, AT_SMEM);

    k_pre1<<<NPART + 512, 256>>>(x, Wq, Wk, Wv, Wout);       // #1
    k_pre2<<<4, 256>>>(nw, nbias);                           // #2
    k_split_x<<<M_TOT / 4, 256>>>(x);                        // #3
    k_mma_gemm<0><<<dim3(12, 992), 128, 65536>>>(nullptr, nullptr, nullptr);  // #4 <- ncu

    k_energy_mma<<<BB, 256, E_SMEM>>>();                     // #5
    k_bn2_fin<<<4, 256>>>(pw, pb);                           // #6
    k_attn_mma<<<BB * 2, 128, AT_SMEM>>>();                  // #7
    k_mma_gemm<1><<<dim3(4, 992), 128, 65536>>>(b_out, x, out);  // #8
}

// round 12
// speedup vs baseline: 1.9533x; 1.2673x over previous
#include <cuda_runtime.h>
#include <cuda_bf16.h>
#include <cstdint>

// Problem constants
#define BB 4096
#define SS 31
#define CC 512
#define HH 8
#define HD 64
#define M_TOT (BB*SS)        // 126976
#define NPOS (SS*SS)         // 961
#define BH (BB*HH)           // 32768
#define EPS 1e-5f
#define INV_SQRT_C 0.044194173824159216f   // 1/sqrt(512)
#define NPART 992            // BN1 partial blocks

// ---------------- scratch (static device memory; no allocations) ----------------
// Packed bf16-split layout: per row of 512, 16 chunks; each chunk = 64 bf16 = [32 hi | 32 lo] (128 B).
__device__ __align__(16) __nv_bfloat16 g_xp[(size_t)M_TOT * 1024];
__device__ __align__(16) __nv_bfloat16 g_ctxp[(size_t)M_TOT * 1024];
__device__ __align__(16) __nv_bfloat16 g_wp[(size_t)1536 * 1024];
__device__ __align__(16) __nv_bfloat16 g_wop[(size_t)512 * 1024];

__device__ __align__(16) __nv_bfloat16 g_qb[(size_t)M_TOT * CC];
__device__ __align__(16) __nv_bfloat16 g_kb[(size_t)M_TOT * CC];
__device__ __align__(16) __nv_bfloat16 g_vb[(size_t)M_TOT * CC];
__device__ __align__(16) float g_energy[(size_t)BH * NPOS];

// BN1 two-phase partials (no atomics)
__device__ __align__(16) float g_psum[(size_t)NPART * CC];
__device__ __align__(16) float g_psq[(size_t)NPART * CC];
__device__ __align__(16) float g_scale[CC];
__device__ __align__(16) float g_shift[CC];
__device__ __align__(16) float g_p_sum[NPOS];
__device__ __align__(16) float g_p_sq[NPOS];
__device__ __align__(16) float g_sc2[NPOS];
__device__ __align__(16) float g_sh2[NPOS];

// ---------------- helpers (family-portable mma/ldmatrix/cp.async) ----------------
__device__ __forceinline__ uint32_t smem_u32(const void* p) {
    uint32_t a;
    asm("{ .reg .u64 t; cvta.to.shared.u64 t, %1; cvt.u32.u64 %0, t; }" : "=r"(a) : "l"(p));
    return a;
}
__device__ __forceinline__ void cp16(uint32_t dst, const void* src) {
    asm volatile("cp.async.cg.shared.global [%0], [%1], 16;" :: "r"(dst), "l"(src) : "memory");
}
__device__ __forceinline__ void cp_commit() {
    asm volatile("cp.async.commit_group;" ::: "memory");
}
__device__ __forceinline__ void cp_wait1() {
    asm volatile("cp.async.wait_group 1;" ::: "memory");
}
__device__ __forceinline__ void cp_wait0() {
    asm volatile("cp.async.wait_group 0;" ::: "memory");
}
__device__ __forceinline__ void ldsm_x4(uint32_t* r, uint32_t addr) {
    asm volatile("ldmatrix.sync.aligned.m8n8.x4.shared.b16 {%0,%1,%2,%3}, [%4];"
                 : "=r"(r[0]), "=r"(r[1]), "=r"(r[2]), "=r"(r[3]) : "r"(addr));
}
__device__ __forceinline__ void mma16816(float* c, const uint32_t* a, const uint32_t* b) {
    asm volatile(
        "mma.sync.aligned.m16n8k16.row.col.f32.bf16.bf16.f32 "
        "{%0,%1,%2,%3}, {%4,%5,%6,%7}, {%8,%9}, {%0,%1,%2,%3};"
        : "+f"(c[0]), "+f"(c[1]), "+f"(c[2]), "+f"(c[3])
        : "r"(a[0]), "r"(a[1]), "r"(a[2]), "r"(a[3]), "r"(b[0]), "r"(b[1]));
}
#define SWZ(off) ((off) ^ (((off) >> 3) & 0x70u))

// ---------------- launch #1: BN1 partial stats + weight split ----------------
__global__ void __launch_bounds__(256) k_pre1(const float* __restrict__ x,
                                              const float* __restrict__ Wq,
                                              const float* __restrict__ Wk,
                                              const float* __restrict__ Wv,
                                              const float* __restrict__ Wo) {
    const int tid = threadIdx.x;
    const int blk = blockIdx.x;
    if (blk < NPART) {
        const size_t r0 = (size_t)blk * 128;
        const float* xp = x + r0 * CC;
        float s0 = 0.f, s1 = 0.f, q0 = 0.f, q1 = 0.f;
        for (int r = 0; r < 128; r++) {
            float v0 = xp[(size_t)r * CC + tid];
            float v1 = xp[(size_t)r * CC + tid + 256];
            s0 += v0; q0 += v0 * v0;
            s1 += v1; q1 += v1 * v1;
        }
        g_psum[(size_t)blk * CC + tid]       = s0;
        g_psq [(size_t)blk * CC + tid]       = q0;
        g_psum[(size_t)blk * CC + tid + 256] = s1;
        g_psq [(size_t)blk * CC + tid + 256] = q1;
    } else {
        int t = (blk - NPART) * 256 + tid;   // [0, 131072)
        int row = t >> 6;
        int oct = t & 63;
        int c = oct >> 2, pos = (oct & 3) << 3, k = oct << 3;
        const float* src;
        __nv_bfloat16* dst;
        if (row < 1536) {
            src = (row < 512) ? (Wq + (size_t)row * 512)
                : (row < 1024) ? (Wk + (size_t)(row - 512) * 512)
                               : (Wv + (size_t)(row - 1024) * 512);
            dst = g_wp + (((size_t)row * 16 + c) << 6) + pos;
        } else {
            int r2 = row - 1536;
            src = Wo + (size_t)r2 * 512;
            dst = g_wop + (((size_t)r2 * 16 + c) << 6) + pos;
        }
        float4 a = *(const float4*)(src + k);
        float4 b = *(const float4*)(src + k + 4);
        float v[8] = {a.x, a.y, a.z, a.w, b.x, b.y, b.z, b.w};
        __nv_bfloat16 hi[8], lo[8];
#pragma unroll
        for (int i = 0; i < 8; i++) {
            hi[i] = __float2bfloat16(v[i]);
            lo[i] = __float2bfloat16(v[i] - __bfloat162float(hi[i]));
        }
        *(uint4*)dst        = *(uint4*)hi;
        *(uint4*)(dst + 32) = *(uint4*)lo;
    }
}

// ---------------- launch #2: BN1 finalize + zero BN2 buffers ----------------
__global__ void __launch_bounds__(256) k_pre2(const float* __restrict__ nw,
                                              const float* __restrict__ nb) {
    const int gid = blockIdx.x * 256 + threadIdx.x;   // <<<4,256>>> -> [0,1024)
    if (gid < CC) {
        float s = 0.f, q = 0.f;
        for (int p = 0; p < NPART; p++) {
            s += g_psum[(size_t)p * CC + gid];
            q += g_psq [(size_t)p * CC + gid];
        }
        const float inv_n = 1.0f / (float)M_TOT;
        float mean = s * inv_n;
        float var  = q * inv_n - mean * mean;
        float rs   = rsqrtf(var + EPS);
        float sc   = rs * nw[gid];
        g_scale[gid] = sc;
        g_shift[gid] = nb[gid] - mean * sc;
    }
    if (gid < NPOS) { g_p_sum[gid] = 0.f; g_p_sq[gid] = 0.f; }
}

// ---------------- launch #3: xn = BN(x), bf16-split, packed ----------------
__global__ void __launch_bounds__(256) k_split_x(const float* __restrict__ x) {
    size_t t = (size_t)blockIdx.x * 256 + threadIdx.x;  // M_TOT*64 threads, 8 elems each
    size_t m = t >> 6;
    int oct = (int)(t & 63);
    int c = oct >> 2, pos = (oct & 3) << 3, k = oct << 3;
    const float* xp = x + m * 512 + k;
    float4 a  = *(const float4*)xp;
    float4 b  = *(const float4*)(xp + 4);
    float4 sA = *(const float4*)(g_scale + k);
    float4 sB = *(const float4*)(g_scale + k + 4);
    float4 hA = *(const float4*)(g_shift + k);
    float4 hB = *(const float4*)(g_shift + k + 4);
    float v[8];
    v[0] = fmaf(a.x, sA.x, hA.x); v[1] = fmaf(a.y, sA.y, hA.y);
    v[2] = fmaf(a.z, sA.z, hA.z); v[3] = fmaf(a.w, sA.w, hA.w);
    v[4] = fmaf(b.x, sB.x, hB.x); v[5] = fmaf(b.y, sB.y, hB.y);
    v[6] = fmaf(b.z, sB.z, hB.z); v[7] = fmaf(b.w, sB.w, hB.w);
    __nv_bfloat16 hi[8], lo[8];
#pragma unroll
    for (int i = 0; i < 8; i++) {
        hi[i] = __float2bfloat16(v[i]);
        lo[i] = __float2bfloat16(v[i] - __bfloat162float(hi[i]));
    }
    __nv_bfloat16* dst = g_xp + ((m * 16 + c) << 6) + pos;
    *(uint4*)dst        = *(uint4*)hi;
    *(uint4*)(dst + 32) = *(uint4*)lo;
}

// ---------------- launch #4: HMMA GEMM (4 warps, 64x64 warp tiles) ----------
// MODE 0: A = g_xp, B = g_wp (1536 rows) -> writes g_qb/g_kb/g_vb bf16.
//   n-blocks 0-7 (q,k): 1-term hi*hi (BN2+1/sqrt(C) make q/k precision uncritical).
//   n-blocks 8-11 (v):  3-term (v error is output-critical).
// MODE 1: A = g_ctxp, B = g_wop (512 rows), 3-term -> out = D + bias + resid (fp32)
template<int MODE>
__global__ void __launch_bounds__(128) k_mma_gemm(const float* __restrict__ bias,
                                                  const float* __restrict__ resid,
                                                  float* __restrict__ Dout) {
    extern __shared__ char sm[];  // 2 stages x (A 16KB + B 16KB) = 64KB
    const int tid = threadIdx.x, lane = tid & 31, w = tid >> 5;
    const int wm = w >> 1, wn = w & 1;
    const int m0 = blockIdx.y * 128, n0g = blockIdx.x * 128;
    const bool full = (MODE == 1) || (blockIdx.x >= 8);
    const __nv_bfloat16* Asrc = (MODE == 0) ? g_xp : g_ctxp;
    const __nv_bfloat16* Bsrc = (MODE == 0) ? g_wp : g_wop;
    const uint32_t sbase = smem_u32(sm);

    float c[4][8][4];
#pragma unroll
    for (int i = 0; i < 4; i++)
#pragma unroll
        for (int j = 0; j < 8; j++)
#pragma unroll
            for (int l = 0; l < 4; l++) c[i][j][l] = 0.f;

    const int a_row = lane & 15;
    const int a_cb  = (lane >> 4) * 16;
    const int b_row = (lane & 7) + ((lane >> 4) & 1) * 8;
    const int b_cb  = ((lane >> 3) & 1) * 16;

    auto load_stage = [&](int st, int ch) {
        uint32_t abase = sbase + st * 32768;
        uint32_t bbase = abase + 16384;
#pragma unroll
        for (int j = 0; j < 8; j++) {
            int u = j * 128 + tid, r = u >> 3, q = u & 7;
            cp16(abase + SWZ((uint32_t)(r * 128 + q * 16)),
                 Asrc + (((size_t)(m0 + r) * 16 + ch) << 6) + q * 8);
        }
#pragma unroll
        for (int j = 0; j < 8; j++) {
            int u = j * 128 + tid, r = u >> 3, q = u & 7;
            cp16(bbase + SWZ((uint32_t)(r * 128 + q * 16)),
                 Bsrc + (((size_t)(n0g + r) * 16 + ch) << 6) + q * 8);
        }
        cp_commit();
    };

    load_stage(0, 0);

    for (int it = 0; it < 16; it++) {
        if (it + 1 < 16) { load_stage((it + 1) & 1, it + 1); cp_wait1(); }
        else             { cp_wait0(); }
        __syncthreads();

        const uint32_t abase = sbase + (it & 1) * 32768;
        const uint32_t bbase = abase + 16384;

#pragma unroll
        for (int ks = 0; ks < 2; ks++) {
            uint32_t ah[16], al[16], bh[16], bl[16];
#pragma unroll
            for (int mi = 0; mi < 4; mi++)
                ldsm_x4(&ah[mi * 4],
                        abase + SWZ((uint32_t)((wm * 64 + mi * 16 + a_row) * 128 + ks * 32 + a_cb)));
#pragma unroll
            for (int nt = 0; nt < 4; nt++)
                ldsm_x4(&bh[nt * 4],
                        bbase + SWZ((uint32_t)((wn * 64 + nt * 16 + b_row) * 128 + ks * 32 + b_cb)));
            // term 1: hiA x hiB
#pragma unroll
            for (int mi = 0; mi < 4; mi++)
#pragma unroll
                for (int nj = 0; nj < 8; nj++)
                    mma16816(c[mi][nj], &ah[mi * 4], &bh[nj * 2]);
            if (full) {
                // term 2: hiA x loB
#pragma unroll
                for (int nt = 0; nt < 4; nt++)
                    ldsm_x4(&bl[nt * 4],
                            bbase + SWZ((uint32_t)((wn * 64 + nt * 16 + b_row) * 128 + 64 + ks * 32 + b_cb)));
#pragma unroll
                for (int mi = 0; mi < 4; mi++)
#pragma unroll
                    for (int nj = 0; nj < 8; nj++)
                        mma16816(c[mi][nj], &ah[mi * 4], &bl[nj * 2]);
                // term 3: loA x hiB
#pragma unroll
                for (int mi = 0; mi < 4; mi++)
                    ldsm_x4(&al[mi * 4],
                            abase + SWZ((uint32_t)((wm * 64 + mi * 16 + a_row) * 128 + 64 + ks * 32 + a_cb)));
#pragma unroll
                for (int mi = 0; mi < 4; mi++)
#pragma unroll
                    for (int nj = 0; nj < 8; nj++)
                        mma16816(c[mi][nj], &al[mi * 4], &bh[nj * 2]);
            }
        }
        __syncthreads();
    }

    // ---------------- epilogue ----------------
    const int r1 = lane >> 2;
    const int c0 = (lane & 3) * 2;
#pragma unroll
    for (int mi = 0; mi < 4; mi++) {
        const int gr = m0 + wm * 64 + mi * 16;
#pragma unroll
        for (int nj = 0; nj < 8; nj++) {
            const int gc = n0g + wn * 64 + nj * 8 + c0;
            if (MODE == 0) {
                const int sel = gc >> 9;
                const int col = gc & 511;
                __nv_bfloat16* op = (sel == 0) ? g_qb : ((sel == 1) ? g_kb : g_vb);
                *(__nv_bfloat162*)(op + (size_t)(gr + r1) * 512 + col) =
                    __floats2bfloat162_rn(c[mi][nj][0], c[mi][nj][1]);
                *(__nv_bfloat162*)(op + (size_t)(gr + r1 + 8) * 512 + col) =
                    __floats2bfloat162_rn(c[mi][nj][2], c[mi][nj][3]);
            } else {
                const int col = gc;
                const float b0 = bias[col], b1 = bias[col + 1];
                {
                    const size_t off = (size_t)(gr + r1) * 512 + col;
                    float2 rv = *(const float2*)(resid + off);
                    *(float2*)(Dout + off) =
                        make_float2(c[mi][nj][0] + b0 + rv.x, c[mi][nj][1] + b1 + rv.y);
                }
                {
                    const size_t off = (size_t)(gr + r1 + 8) * 512 + col;
                    float2 rv = *(const float2*)(resid + off);
                    *(float2*)(Dout + off) =
                        make_float2(c[mi][nj][2] + b0 + rv.x, c[mi][nj][3] + b1 + rv.y);
                }
            }
        }
    }
}

// ---------------- launch #5: energy via bf16 MMA + fused BN2 partials ----------------
#define ET_ROWB 144
#define ET_SZ  (32 * ET_ROWB)          // 4608 B per head tile
#define E_SMEM (16 * ET_SZ)            // q tiles [8] + k tiles [8] = 73728 B

__global__ void __launch_bounds__(256) k_energy_mma() {
    extern __shared__ char sm[];
    const int tid = threadIdx.x, lane = tid & 31, w = tid >> 5;   // w = head
    const int b = blockIdx.x;
    const uint32_t sbase = smem_u32(sm);
    const uint32_t qt = sbase + w * ET_SZ;
    const uint32_t kt = sbase + 8 * ET_SZ + w * ET_SZ;

    const __nv_bfloat16* qsrc = g_qb + (size_t)(b * SS) * 512 + w * 64;
    const __nv_bfloat16* ksrc = g_kb + (size_t)(b * SS) * 512 + w * 64;
    for (int i = lane; i < 248; i += 32) {
        int row = i >> 3, q8 = i & 7;
        cp16(qt + row * ET_ROWB + q8 * 16, qsrc + (size_t)row * 512 + q8 * 8);
        cp16(kt + row * ET_ROWB + q8 * 16, ksrc + (size_t)row * 512 + q8 * 8);
    }
    cp_commit();
    cp_wait0();
    if (lane < 16) {
        uint32_t base = (lane < 8) ? qt : kt;
        int q8 = lane & 7;
        uint4 z = make_uint4(0u, 0u, 0u, 0u);
        *(uint4*)(sm + (base - sbase) + 31 * ET_ROWB + q8 * 16) = z;
    }
    __syncthreads();

    float c[2][4][4];
#pragma unroll
    for (int i = 0; i < 2; i++)
#pragma unroll
        for (int j = 0; j < 4; j++)
#pragma unroll
            for (int l = 0; l < 4; l++) c[i][j][l] = 0.f;

    const int a_row = lane & 15;
    const int a_cb  = (lane >> 4) * 16;
    const int b_row = (lane & 7) + ((lane >> 4) & 1) * 8;
    const int b_cb  = ((lane >> 3) & 1) * 16;

#pragma unroll
    for (int ks = 0; ks < 4; ks++) {
        uint32_t af[2][4], bf[8];
#pragma unroll
        for (int mi = 0; mi < 2; mi++)
            ldsm_x4(af[mi], qt + (mi * 16 + a_row) * ET_ROWB + ks * 32 + a_cb);
#pragma unroll
        for (int g = 0; g < 2; g++)
            ldsm_x4(&bf[g * 4], kt + (g * 16 + b_row) * ET_ROWB + ks * 32 + b_cb);
#pragma unroll
        for (int mi = 0; mi < 2; mi++)
#pragma unroll
            for (int nj = 0; nj < 4; nj++)
                mma16816(c[mi][nj], af[mi], &bf[nj * 2]);
    }
    __syncthreads();   // tiles dead; reuse smem as staging

    float* stage = (float*)sm;   // [8][32*32]
    const int r0 = lane >> 2, c0 = (lane & 3) * 2;
#pragma unroll
    for (int mi = 0; mi < 2; mi++)
#pragma unroll
        for (int nj = 0; nj < 4; nj++) {
            int rr = mi * 16 + r0, cc = nj * 8 + c0;
            stage[w * 1024 + rr * 32 + cc]           = c[mi][nj][0];
            stage[w * 1024 + rr * 32 + cc + 1]       = c[mi][nj][1];
            stage[w * 1024 + (rr + 8) * 32 + cc]     = c[mi][nj][2];
            stage[w * 1024 + (rr + 8) * 32 + cc + 1] = c[mi][nj][3];
        }
    __syncthreads();

    float* ebase = g_energy + (size_t)(b * 8) * NPOS;
    for (int p = tid; p < NPOS; p += 256) {
        int r = p / SS, cph = p - r * SS;
        int idx = r * 32 + cph;
        float s = 0.f, q = 0.f;
#pragma unroll
        for (int h = 0; h < 8; h++) {
            float v = stage[h * 1024 + idx];
            ebase[(size_t)h * NPOS + p] = v;
            s += v; q += v * v;
        }
        atomicAdd(&g_p_sum[p], s);
        atomicAdd(&g_p_sq[p],  q);
    }
}

// ---------------- launch #6: BN2 finalize ----------------
__global__ void k_bn2_fin(const float* __restrict__ pw, const float* __restrict__ pb) {
    int i = blockIdx.x * blockDim.x + threadIdx.x;  // <<<4,256>>>
    if (i >= NPOS) return;
    float inv_n = 1.0f / (float)BH;
    float mean = g_p_sum[i] * inv_n;
    float var  = g_p_sq[i] * inv_n - mean * mean;
    float rs   = rsqrtf(var + EPS);
    float a    = rs * pw[i] * INV_SQRT_C;
    g_sc2[i] = a;
    g_sh2[i] = pb[i] * INV_SQRT_C - mean * a;
}

// ---------------- launch #7: softmax + AV via bf16 MMA; writes split ctx -------------
#define AT_SMEM 57344

__global__ void __launch_bounds__(128) k_attn_mma() {
    extern __shared__ char smA[];
    const int tid = threadIdx.x, lane = tid & 31, w = tid >> 5;
    const int b = blockIdx.x >> 1;
    const int h = ((blockIdx.x & 1) << 2) + w;
    const uint32_t sbase = smem_u32(smA);
    char* e_t   = smA + w * 4096;
    char* phi_p = smA + 16384 + w * 2560;
    char* plo_p = smA + 26624 + w * 2560;
    char* vt_p  = smA + 36864 + w * 5120;
    const uint32_t phi = sbase + 16384 + w * 2560;
    const uint32_t plo = sbase + 26624 + w * 2560;
    const uint32_t vt  = sbase + 36864 + w * 5120;

    for (int i = lane; i < 640; i += 32) {
        ((uint32_t*)phi_p)[i] = 0u;
        ((uint32_t*)plo_p)[i] = 0u;
    }
    for (int d = lane; d < 64; d += 32)
        *(__nv_bfloat16*)(vt_p + d * 80 + 62) = __float2bfloat16(0.f);

    const float* ep = g_energy + (size_t)(b * 8 + h) * NPOS;
    for (int p = lane; p < NPOS; p += 32) {
        float v = fmaf(ep[p], g_sc2[p], g_sh2[p]);
        int r = p / SS, cc = p - r * SS;
        ((float*)e_t)[r * 33 + cc] = v;
    }
    const __nv_bfloat16* vp = g_vb + (size_t)(b * SS) * 512 + h * 64;
    for (int i = lane; i < SS * 16; i += 32) {
        int s = i >> 4, d0 = (i & 15) << 2;
        __nv_bfloat16 tmp[4];
        *(uint2*)tmp = *(const uint2*)(vp + (size_t)s * 512 + d0);
#pragma unroll
        for (int j = 0; j < 4; j++)
            *(__nv_bfloat16*)(vt_p + (d0 + j) * 80 + s * 2) = tmp[j];
    }
    __syncwarp();

    if (lane < SS) {
        float* row = (float*)e_t + lane * 33;
        float mx = -1e30f;
#pragma unroll
        for (int cc = 0; cc < SS; cc++) mx = fmaxf(mx, row[cc]);
        float sum = 0.f;
#pragma unroll
        for (int cc = 0; cc < SS; cc++) {
            float t = __expf(row[cc] - mx);
            row[cc] = t; sum += t;
        }
        float inv = 1.0f / sum;
#pragma unroll
        for (int cc = 0; cc < SS; cc++) {
            float p = row[cc] * inv;
            __nv_bfloat16 hi = __float2bfloat16(p);
            __nv_bfloat16 lo = __float2bfloat16(p - __bfloat162float(hi));
            *(__nv_bfloat16*)(phi_p + lane * 80 + cc * 2) = hi;
            *(__nv_bfloat16*)(plo_p + lane * 80 + cc * 2) = lo;
        }
    }
    __syncwarp();

    float acc[2][8][4];
#pragma unroll
    for (int i = 0; i < 2; i++)
#pragma unroll
        for (int j = 0; j < 8; j++)
#pragma unroll
            for (int l = 0; l < 4; l++) acc[i][j][l] = 0.f;

    const int a_row = lane & 15;
    const int a_cb  = (lane >> 4) * 16;
    const int b_row = (lane & 7) + ((lane >> 4) & 1) * 8;
    const int b_cb  = ((lane >> 3) & 1) * 16;

#pragma unroll
    for (int ks = 0; ks < 2; ks++) {
        uint32_t pf[2][4], lf[2][4], bfr[16];
#pragma unroll
        for (int mi = 0; mi < 2; mi++) {
            ldsm_x4(pf[mi], phi + (mi * 16 + a_row) * 80 + ks * 32 + a_cb);
            ldsm_x4(lf[mi], plo + (mi * 16 + a_row) * 80 + ks * 32 + a_cb);
        }
#pragma unroll
        for (int nt = 0; nt < 4; nt++)
            ldsm_x4(&bfr[nt * 4], vt + (nt * 16 + b_row) * 80 + ks * 32 + b_cb);
#pragma unroll
        for (int mi = 0; mi < 2; mi++)
#pragma unroll
            for (int nj = 0; nj < 8; nj++)
                mma16816(acc[mi][nj], pf[mi], &bfr[nj * 2]);
#pragma unroll
        for (int mi = 0; mi < 2; mi++)
#pragma unroll
            for (int nj = 0; nj < 8; nj++)
                mma16816(acc[mi][nj], lf[mi], &bfr[nj * 2]);
    }

    const int r1 = lane >> 2, c0 = (lane & 3) * 2;
#pragma unroll
    for (int mi = 0; mi < 2; mi++) {
#pragma unroll
        for (int nj = 0; nj < 8; nj++) {
            const int d = nj * 8 + c0;
            const int colg = h * 64 + d;
            const int chunk = colg >> 5, pos = colg & 31;
            const int q1 = mi * 16 + r1;
            const int q2 = q1 + 8;
            {
                float v0 = acc[mi][nj][0], v1 = acc[mi][nj][1];
                __nv_bfloat16 h0 = __float2bfloat16(v0), h1 = __float2bfloat16(v1);
                __nv_bfloat162 hh; hh.x = h0; hh.y = h1;
                __nv_bfloat162 ll;
                ll.x = __float2bfloat16(v0 - __bfloat162float(h0));
                ll.y = __float2bfloat16(v1 - __bfloat162float(h1));
                size_t base = ((((size_t)b * 31 + q1) * 16 + chunk) << 6) + pos;
                *(__nv_bfloat162*)(g_ctxp + base)      = hh;
                *(__nv_bfloat162*)(g_ctxp + base + 32) = ll;
            }
            if (q2 < 31) {
                float v0 = acc[mi][nj][2], v1 = acc[mi][nj][3];
                __nv_bfloat16 h0 = __float2bfloat16(v0), h1 = __float2bfloat16(v1);
                __nv_bfloat162 hh; hh.x = h0; hh.y = h1;
                __nv_bfloat162 ll;
                ll.x = __float2bfloat16(v0 - __bfloat162float(h0));
                ll.y = __float2bfloat16(v1 - __bfloat162float(h1));
                size_t base = ((((size_t)b * 31 + q2) * 16 + chunk) << 6) + pos;
                *(__nv_bfloat162*)(g_ctxp + base)      = hh;
                *(__nv_bfloat162*)(g_ctxp + base + 32) = ll;
            }
        }
    }
}

// ---------------- launch ----------------
extern "C" void kernel_launch(void* const* d_in, const int* in_sizes, int n_in,
                              void* d_out, int out_size) {
    const float* x     = (const float*)d_in[0];
    const float* nw    = (const float*)d_in[1];
    const float* nbias = (const float*)d_in[2];
    const float* Wq    = (const float*)d_in[3];
    const float* Wk    = (const float*)d_in[4];
    const float* Wv    = (const float*)d_in[5];
    const float* Wout  = (const float*)d_in[6];
    const float* b_out = (const float*)d_in[7];
    const float* pw    = (const float*)d_in[8];
    const float* pb    = (const float*)d_in[9];
    float* out = (float*)d_out;

    cudaFuncSetAttribute(k_mma_gemm<0>, cudaFuncAttributeMaxDynamicSharedMemorySize, 65536);
    cudaFuncSetAttribute(k_mma_gemm<1>, cudaFuncAttributeMaxDynamicSharedMemorySize, 65536);
    cudaFuncSetAttribute(k_energy_mma, cudaFuncAttributeMaxDynamicSharedMemorySize, E_SMEM);
    cudaFuncSetAttribute(k_attn_mma, cudaFuncAttributeMaxDynamicSharedMemorySize, AT_SMEM);

    k_pre1<<<NPART + 512, 256>>>(x, Wq, Wk, Wv, Wout);       // #1
    k_pre2<<<4, 256>>>(nw, nbias);                           // #2
    k_split_x<<<M_TOT / 4, 256>>>(x);                        // #3
    k_mma_gemm<0><<<dim3(12, 992), 128, 65536>>>(nullptr, nullptr, nullptr);  // #4 <- ncu

    k_energy_mma<<<BB, 256, E_SMEM>>>();                     // #5
    k_bn2_fin<<<4, 256>>>(pw, pb);                           // #6
    k_attn_mma<<<BB * 2, 128, AT_SMEM>>>();                  // #7
    k_mma_gemm<1><<<dim3(4, 992), 128, 65536>>>(b_out, x, out);  // #8
}

// round 13
// speedup vs baseline: 2.0871x; 1.0685x over previous
#include <cuda_runtime.h>
#include <cuda_bf16.h>
#include <cstdint>

// Problem constants
#define BB 4096
#define SS 31
#define CC 512
#define HH 8
#define HD 64
#define M_TOT (BB*SS)        // 126976
#define NPOS (SS*SS)         // 961
#define BH (BB*HH)           // 32768
#define EPS 1e-5f
#define INV_SQRT_C 0.044194173824159216f   // 1/sqrt(512)
#define NPART 992            // BN1 partial blocks

// ---------------- scratch (static device memory; no allocations) ----------------
__device__ __align__(16) __nv_bfloat16 g_xb[(size_t)M_TOT * 512];    // BN(x), hi only
__device__ __align__(16) __nv_bfloat16 g_ctxb[(size_t)M_TOT * 512];  // ctx, plain bf16
// Weights stay packed: per row 16 chunks of [32 hi | 32 lo] bf16 (128 B/chunk).
__device__ __align__(16) __nv_bfloat16 g_wp[(size_t)1536 * 1024];
__device__ __align__(16) __nv_bfloat16 g_wop[(size_t)512 * 1024];

__device__ __align__(16) __nv_bfloat16 g_qb[(size_t)M_TOT * CC];
__device__ __align__(16) __nv_bfloat16 g_kb[(size_t)M_TOT * CC];
__device__ __align__(16) float g_vf[(size_t)M_TOT * CC];             // v in fp32
__device__ __align__(16) float g_energy[(size_t)BH * NPOS];

// BN1 two-phase partials (no atomics)
__device__ __align__(16) float g_psum[(size_t)NPART * CC];
__device__ __align__(16) float g_psq[(size_t)NPART * CC];
__device__ __align__(16) float g_scale[CC];
__device__ __align__(16) float g_shift[CC];
__device__ __align__(16) float g_p_sum[NPOS];
__device__ __align__(16) float g_p_sq[NPOS];
__device__ __align__(16) float g_sc2[NPOS];
__device__ __align__(16) float g_sh2[NPOS];

// ---------------- helpers ----------------
__device__ __forceinline__ uint32_t smem_u32(const void* p) {
    uint32_t a;
    asm("{ .reg .u64 t; cvta.to.shared.u64 t, %1; cvt.u32.u64 %0, t; }" : "=r"(a) : "l"(p));
    return a;
}
__device__ __forceinline__ void cp16(uint32_t dst, const void* src) {
    asm volatile("cp.async.cg.shared.global [%0], [%1], 16;" :: "r"(dst), "l"(src) : "memory");
}
__device__ __forceinline__ void cp_commit() {
    asm volatile("cp.async.commit_group;" ::: "memory");
}
__device__ __forceinline__ void cp_wait1() {
    asm volatile("cp.async.wait_group 1;" ::: "memory");
}
__device__ __forceinline__ void cp_wait0() {
    asm volatile("cp.async.wait_group 0;" ::: "memory");
}
__device__ __forceinline__ void ldsm_x4(uint32_t* r, uint32_t addr) {
    asm volatile("ldmatrix.sync.aligned.m8n8.x4.shared.b16 {%0,%1,%2,%3}, [%4];"
                 : "=r"(r[0]), "=r"(r[1]), "=r"(r[2]), "=r"(r[3]) : "r"(addr));
}
__device__ __forceinline__ void mma16816(float* c, const uint32_t* a, const uint32_t* b) {
    asm volatile(
        "mma.sync.aligned.m16n8k16.row.col.f32.bf16.bf16.f32 "
        "{%0,%1,%2,%3}, {%4,%5,%6,%7}, {%8,%9}, {%0,%1,%2,%3};"
        : "+f"(c[0]), "+f"(c[1]), "+f"(c[2]), "+f"(c[3])
        : "r"(a[0]), "r"(a[1]), "r"(a[2]), "r"(a[3]), "r"(b[0]), "r"(b[1]));
}
#define SWZ(off) ((off) ^ (((off) >> 3) & 0x70u))

// ---------------- launch #1: BN1 partial stats + weight split (packed) --------------
__global__ void __launch_bounds__(256) k_pre1(const float* __restrict__ x,
                                              const float* __restrict__ Wq,
                                              const float* __restrict__ Wk,
                                              const float* __restrict__ Wv,
                                              const float* __restrict__ Wo) {
    const int tid = threadIdx.x;
    const int blk = blockIdx.x;
    if (blk < NPART) {
        const size_t r0 = (size_t)blk * 128;
        const float* xp = x + r0 * CC;
        float s0 = 0.f, s1 = 0.f, q0 = 0.f, q1 = 0.f;
        for (int r = 0; r < 128; r++) {
            float v0 = xp[(size_t)r * CC + tid];
            float v1 = xp[(size_t)r * CC + tid + 256];
            s0 += v0; q0 += v0 * v0;
            s1 += v1; q1 += v1 * v1;
        }
        g_psum[(size_t)blk * CC + tid]       = s0;
        g_psq [(size_t)blk * CC + tid]       = q0;
        g_psum[(size_t)blk * CC + tid + 256] = s1;
        g_psq [(size_t)blk * CC + tid + 256] = q1;
    } else {
        int t = (blk - NPART) * 256 + tid;   // [0, 131072)
        int row = t >> 6;
        int oct = t & 63;
        int c = oct >> 2, pos = (oct & 3) << 3, k = oct << 3;
        const float* src;
        __nv_bfloat16* dst;
        if (row < 1536) {
            src = (row < 512) ? (Wq + (size_t)row * 512)
                : (row < 1024) ? (Wk + (size_t)(row - 512) * 512)
                               : (Wv + (size_t)(row - 1024) * 512);
            dst = g_wp + (((size_t)row * 16 + c) << 6) + pos;
        } else {
            int r2 = row - 1536;
            src = Wo + (size_t)r2 * 512;
            dst = g_wop + (((size_t)r2 * 16 + c) << 6) + pos;
        }
        float4 a = *(const float4*)(src + k);
        float4 b = *(const float4*)(src + k + 4);
        float v[8] = {a.x, a.y, a.z, a.w, b.x, b.y, b.z, b.w};
        __nv_bfloat16 hi[8], lo[8];
#pragma unroll
        for (int i = 0; i < 8; i++) {
            hi[i] = __float2bfloat16(v[i]);
            lo[i] = __float2bfloat16(v[i] - __bfloat162float(hi[i]));
        }
        *(uint4*)dst        = *(uint4*)hi;
        *(uint4*)(dst + 32) = *(uint4*)lo;
    }
}

// ---------------- launch #2: BN1 finalize + zero BN2 buffers ----------------
__global__ void __launch_bounds__(256) k_pre2(const float* __restrict__ nw,
                                              const float* __restrict__ nb) {
    const int gid = blockIdx.x * 256 + threadIdx.x;   // <<<4,256>>> -> [0,1024)
    if (gid < CC) {
        float s = 0.f, q = 0.f;
        for (int p = 0; p < NPART; p++) {
            s += g_psum[(size_t)p * CC + gid];
            q += g_psq [(size_t)p * CC + gid];
        }
        const float inv_n = 1.0f / (float)M_TOT;
        float mean = s * inv_n;
        float var  = q * inv_n - mean * mean;
        float rs   = rsqrtf(var + EPS);
        float sc   = rs * nw[gid];
        g_scale[gid] = sc;
        g_shift[gid] = nb[gid] - mean * sc;
    }
    if (gid < NPOS) { g_p_sum[gid] = 0.f; g_p_sq[gid] = 0.f; }
}

// ---------------- launch #3: xn = BN(x) -> plain bf16 ----------------
__global__ void __launch_bounds__(256) k_split_x(const float* __restrict__ x) {
    size_t t = (size_t)blockIdx.x * 256 + threadIdx.x;
    size_t m = t >> 6;
    int k = (int)(t & 63) * 8;
    const float* xp = x + m * 512 + k;
    float4 a  = *(const float4*)xp;
    float4 b  = *(const float4*)(xp + 4);
    float4 sA = *(const float4*)(g_scale + k);
    float4 sB = *(const float4*)(g_scale + k + 4);
    float4 hA = *(const float4*)(g_shift + k);
    float4 hB = *(const float4*)(g_shift + k + 4);
    __nv_bfloat16 hb[8];
    hb[0] = __float2bfloat16(fmaf(a.x, sA.x, hA.x));
    hb[1] = __float2bfloat16(fmaf(a.y, sA.y, hA.y));
    hb[2] = __float2bfloat16(fmaf(a.z, sA.z, hA.z));
    hb[3] = __float2bfloat16(fmaf(a.w, sA.w, hA.w));
    hb[4] = __float2bfloat16(fmaf(b.x, sB.x, hB.x));
    hb[5] = __float2bfloat16(fmaf(b.y, sB.y, hB.y));
    hb[6] = __float2bfloat16(fmaf(b.z, sB.z, hB.z));
    hb[7] = __float2bfloat16(fmaf(b.w, sB.w, hB.w));
    *(uint4*)(g_xb + m * 512 + k) = *(uint4*)hb;
}

// ---------------- 1-term GEMM: hi-only 128-B stages, 8 iterations ----------------
// MODE 0: A = g_xb, B = g_wp rows [0,1024) -> q/k bf16
// MODE 1: A = g_ctxb, B = g_wop -> out = D + bias + resid (fp32)
template<int MODE>
__global__ void __launch_bounds__(128) k_gemm_1t(const float* __restrict__ bias,
                                                 const float* __restrict__ resid,
                                                 float* __restrict__ Dout) {
    extern __shared__ char sm[];  // 2 stages x (A 16KB + B 16KB) = 64KB
    const int tid = threadIdx.x, lane = tid & 31, w = tid >> 5;
    const int wm = w >> 1, wn = w & 1;
    const int m0 = blockIdx.y * 128, n0g = blockIdx.x * 128;
    const __nv_bfloat16* Asrc = (MODE == 0) ? g_xb : g_ctxb;
    const __nv_bfloat16* Bsrc = (MODE == 0) ? g_wp : g_wop;
    const uint32_t sbase = smem_u32(sm);

    float c[4][8][4];
#pragma unroll
    for (int i = 0; i < 4; i++)
#pragma unroll
        for (int j = 0; j < 8; j++)
#pragma unroll
            for (int l = 0; l < 4; l++) c[i][j][l] = 0.f;

    const int a_row = lane & 15;
    const int a_cb  = (lane >> 4) * 16;
    const int b_row = (lane & 7) + ((lane >> 4) & 1) * 8;
    const int b_cb  = ((lane >> 3) & 1) * 16;

    // stage s covers k-cols [64s, 64s+64): A plain rows; B = hi halves of chunks 2s,2s+1
    auto load_stage = [&](int st, int s) {
        uint32_t abase = sbase + st * 32768;
        uint32_t bbase = abase + 16384;
#pragma unroll
        for (int j = 0; j < 8; j++) {
            int u = j * 128 + tid, r = u >> 3, q8 = u & 7;
            cp16(abase + SWZ((uint32_t)(r * 128 + q8 * 16)),
                 Asrc + (size_t)(m0 + r) * 512 + 64 * s + q8 * 8);
        }
#pragma unroll
        for (int j = 0; j < 8; j++) {
            int u = j * 128 + tid, r = u >> 3, q8 = u & 7;
            cp16(bbase + SWZ((uint32_t)(r * 128 + q8 * 16)),
                 Bsrc + (((size_t)(n0g + r) * 16 + 2 * s + (q8 >> 2)) << 6) + (q8 & 3) * 8);
        }
        cp_commit();
    };

    load_stage(0, 0);

    for (int it = 0; it < 8; it++) {
        if (it + 1 < 8) { load_stage((it + 1) & 1, it + 1); cp_wait1(); }
        else            { cp_wait0(); }
        __syncthreads();

        const uint32_t abase = sbase + (it & 1) * 32768;
        const uint32_t bbase = abase + 16384;

#pragma unroll
        for (int ks = 0; ks < 4; ks++) {
            uint32_t ah[16], bh[16];
#pragma unroll
            for (int mi = 0; mi < 4; mi++)
                ldsm_x4(&ah[mi * 4],
                        abase + SWZ((uint32_t)((wm * 64 + mi * 16 + a_row) * 128 + ks * 32 + a_cb)));
#pragma unroll
            for (int nt = 0; nt < 4; nt++)
                ldsm_x4(&bh[nt * 4],
                        bbase + SWZ((uint32_t)((wn * 64 + nt * 16 + b_row) * 128 + ks * 32 + b_cb)));
#pragma unroll
            for (int mi = 0; mi < 4; mi++)
#pragma unroll
                for (int nj = 0; nj < 8; nj++)
                    mma16816(c[mi][nj], &ah[mi * 4], &bh[nj * 2]);
        }
        __syncthreads();
    }

    const int r1 = lane >> 2;
    const int c0 = (lane & 3) * 2;
#pragma unroll
    for (int mi = 0; mi < 4; mi++) {
        const int gr = m0 + wm * 64 + mi * 16;
#pragma unroll
        for (int nj = 0; nj < 8; nj++) {
            const int gc = n0g + wn * 64 + nj * 8 + c0;
            if (MODE == 0) {
                const int sel = gc >> 9;
                const int col = gc & 511;
                __nv_bfloat16* op = (sel == 0) ? g_qb : g_kb;
                *(__nv_bfloat162*)(op + (size_t)(gr + r1) * 512 + col) =
                    __floats2bfloat162_rn(c[mi][nj][0], c[mi][nj][1]);
                *(__nv_bfloat162*)(op + (size_t)(gr + r1 + 8) * 512 + col) =
                    __floats2bfloat162_rn(c[mi][nj][2], c[mi][nj][3]);
            } else {
                const int col = gc;
                const float b0 = bias[col], b1 = bias[col + 1];
                {
                    const size_t off = (size_t)(gr + r1) * 512 + col;
                    float2 rv = *(const float2*)(resid + off);
                    *(float2*)(Dout + off) =
                        make_float2(c[mi][nj][0] + b0 + rv.x, c[mi][nj][1] + b1 + rv.y);
                }
                {
                    const size_t off = (size_t)(gr + r1 + 8) * 512 + col;
                    float2 rv = *(const float2*)(resid + off);
                    *(float2*)(Dout + off) =
                        make_float2(c[mi][nj][2] + b0 + rv.x, c[mi][nj][3] + b1 + rv.y);
                }
            }
        }
    }
}

// ---------------- v GEMM: 2-term (Ah*Bh + Ah*Bl), A hi-only, v stored fp32 ----------
// Stage: A tile 128 rows x 80B (64B data + pad, no swizzle) + B packed chunk 16KB.
__global__ void __launch_bounds__(128) k_gemm_v() {
    extern __shared__ char sm[];  // 2 x (10240 + 16384) = 53248
    const int tid = threadIdx.x, lane = tid & 31, w = tid >> 5;
    const int wm = w >> 1, wn = w & 1;
    const int m0 = blockIdx.y * 128, nb = blockIdx.x * 128;  // nb in [0,512)
    const uint32_t sbase = smem_u32(sm);

    float c[4][8][4];
#pragma unroll
    for (int i = 0; i < 4; i++)
#pragma unroll
        for (int j = 0; j < 8; j++)
#pragma unroll
            for (int l = 0; l < 4; l++) c[i][j][l] = 0.f;

    const int a_row = lane & 15;
    const int a_cb  = (lane >> 4) * 16;
    const int b_row = (lane & 7) + ((lane >> 4) & 1) * 8;
    const int b_cb  = ((lane >> 3) & 1) * 16;

    auto load_stage = [&](int st, int ch) {
        uint32_t abase = sbase + st * 26624;
        uint32_t bbase = abase + 10240;
#pragma unroll
        for (int j = 0; j < 4; j++) {
            int u = j * 128 + tid, r = u >> 2, q8 = u & 3;
            cp16(abase + (uint32_t)(r * 80 + q8 * 16),
                 g_xb + (size_t)(m0 + r) * 512 + 32 * ch + q8 * 8);
        }
#pragma unroll
        for (int j = 0; j < 8; j++) {
            int u = j * 128 + tid, r = u >> 3, q8 = u & 7;
            cp16(bbase + SWZ((uint32_t)(r * 128 + q8 * 16)),
                 g_wp + (((size_t)(1024 + nb + r) * 16 + ch) << 6) + q8 * 8);
        }
        cp_commit();
    };

    load_stage(0, 0);

    for (int it = 0; it < 16; it++) {
        if (it + 1 < 16) { load_stage((it + 1) & 1, it + 1); cp_wait1(); }
        else             { cp_wait0(); }
        __syncthreads();

        const uint32_t abase = sbase + (it & 1) * 26624;
        const uint32_t bbase = abase + 10240;

#pragma unroll
        for (int ks = 0; ks < 2; ks++) {
            uint32_t ah[16], bh[16], bl[16];
#pragma unroll
            for (int mi = 0; mi < 4; mi++)
                ldsm_x4(&ah[mi * 4],
                        abase + (uint32_t)((wm * 64 + mi * 16 + a_row) * 80 + ks * 32 + a_cb));
#pragma unroll
            for (int nt = 0; nt < 4; nt++)
                ldsm_x4(&bh[nt * 4],
                        bbase + SWZ((uint32_t)((wn * 64 + nt * 16 + b_row) * 128 + ks * 32 + b_cb)));
#pragma unroll
            for (int mi = 0; mi < 4; mi++)
#pragma unroll
                for (int nj = 0; nj < 8; nj++)
                    mma16816(c[mi][nj], &ah[mi * 4], &bh[nj * 2]);
#pragma unroll
            for (int nt = 0; nt < 4; nt++)
                ldsm_x4(&bl[nt * 4],
                        bbase + SWZ((uint32_t)((wn * 64 + nt * 16 + b_row) * 128 + 64 + ks * 32 + b_cb)));
#pragma unroll
            for (int mi = 0; mi < 4; mi++)
#pragma unroll
                for (int nj = 0; nj < 8; nj++)
                    mma16816(c[mi][nj], &ah[mi * 4], &bl[nj * 2]);
        }
        __syncthreads();
    }

    const int r1 = lane >> 2;
    const int c0 = (lane & 3) * 2;
#pragma unroll
    for (int mi = 0; mi < 4; mi++) {
        const int gr = m0 + wm * 64 + mi * 16;
#pragma unroll
        for (int nj = 0; nj < 8; nj++) {
            const int col = nb + wn * 64 + nj * 8 + c0;
            *(float2*)(g_vf + (size_t)(gr + r1) * 512 + col) =
                make_float2(c[mi][nj][0], c[mi][nj][1]);
            *(float2*)(g_vf + (size_t)(gr + r1 + 8) * 512 + col) =
                make_float2(c[mi][nj][2], c[mi][nj][3]);
        }
    }
}

// ---------------- energy via bf16 MMA + fused BN2 partials ----------------
#define ET_ROWB 144
#define ET_SZ  (32 * ET_ROWB)
#define E_SMEM (16 * ET_SZ)            // 73728 B

__global__ void __launch_bounds__(256) k_energy_mma() {
    extern __shared__ char sm[];
    const int tid = threadIdx.x, lane = tid & 31, w = tid >> 5;   // w = head
    const int b = blockIdx.x;
    const uint32_t sbase = smem_u32(sm);
    const uint32_t qt = sbase + w * ET_SZ;
    const uint32_t kt = sbase + 8 * ET_SZ + w * ET_SZ;

    const __nv_bfloat16* qsrc = g_qb + (size_t)(b * SS) * 512 + w * 64;
    const __nv_bfloat16* ksrc = g_kb + (size_t)(b * SS) * 512 + w * 64;
    for (int i = lane; i < 248; i += 32) {
        int row = i >> 3, q8 = i & 7;
        cp16(qt + row * ET_ROWB + q8 * 16, qsrc + (size_t)row * 512 + q8 * 8);
        cp16(kt + row * ET_ROWB + q8 * 16, ksrc + (size_t)row * 512 + q8 * 8);
    }
    cp_commit();
    cp_wait0();
    if (lane < 16) {
        uint32_t base = (lane < 8) ? qt : kt;
        int q8 = lane & 7;
        uint4 z = make_uint4(0u, 0u, 0u, 0u);
        *(uint4*)(sm + (base - sbase) + 31 * ET_ROWB + q8 * 16) = z;
    }
    __syncthreads();

    float c[2][4][4];
#pragma unroll
    for (int i = 0; i < 2; i++)
#pragma unroll
        for (int j = 0; j < 4; j++)
#pragma unroll
            for (int l = 0; l < 4; l++) c[i][j][l] = 0.f;

    const int a_row = lane & 15;
    const int a_cb  = (lane >> 4) * 16;
    const int b_row = (lane & 7) + ((lane >> 4) & 1) * 8;
    const int b_cb  = ((lane >> 3) & 1) * 16;

#pragma unroll
    for (int ks = 0; ks < 4; ks++) {
        uint32_t af[2][4], bf[8];
#pragma unroll
        for (int mi = 0; mi < 2; mi++)
            ldsm_x4(af[mi], qt + (mi * 16 + a_row) * ET_ROWB + ks * 32 + a_cb);
#pragma unroll
        for (int g = 0; g < 2; g++)
            ldsm_x4(&bf[g * 4], kt + (g * 16 + b_row) * ET_ROWB + ks * 32 + b_cb);
#pragma unroll
        for (int mi = 0; mi < 2; mi++)
#pragma unroll
            for (int nj = 0; nj < 4; nj++)
                mma16816(c[mi][nj], af[mi], &bf[nj * 2]);
    }
    __syncthreads();

    float* stage = (float*)sm;
    const int r0 = lane >> 2, c0 = (lane & 3) * 2;
#pragma unroll
    for (int mi = 0; mi < 2; mi++)
#pragma unroll
        for (int nj = 0; nj < 4; nj++) {
            int rr = mi * 16 + r0, cc = nj * 8 + c0;
            stage[w * 1024 + rr * 32 + cc]           = c[mi][nj][0];
            stage[w * 1024 + rr * 32 + cc + 1]       = c[mi][nj][1];
            stage[w * 1024 + (rr + 8) * 32 + cc]     = c[mi][nj][2];
            stage[w * 1024 + (rr + 8) * 32 + cc + 1] = c[mi][nj][3];
        }
    __syncthreads();

    float* ebase = g_energy + (size_t)(b * 8) * NPOS;
    for (int p = tid; p < NPOS; p += 256) {
        int r = p / SS, cph = p - r * SS;
        int idx = r * 32 + cph;
        float s = 0.f, q = 0.f;
#pragma unroll
        for (int h = 0; h < 8; h++) {
            float v = stage[h * 1024 + idx];
            ebase[(size_t)h * NPOS + p] = v;
            s += v; q += v * v;
        }
        atomicAdd(&g_p_sum[p], s);
        atomicAdd(&g_p_sq[p],  q);
    }
}

// ---------------- BN2 finalize ----------------
__global__ void k_bn2_fin(const float* __restrict__ pw, const float* __restrict__ pb) {
    int i = blockIdx.x * blockDim.x + threadIdx.x;
    if (i >= NPOS) return;
    float inv_n = 1.0f / (float)BH;
    float mean = g_p_sum[i] * inv_n;
    float var  = g_p_sq[i] * inv_n - mean * mean;
    float rs   = rsqrtf(var + EPS);
    float a    = rs * pw[i] * INV_SQRT_C;
    g_sc2[i] = a;
    g_sh2[i] = pb[i] * INV_SQRT_C - mean * a;
}

// ---------------- softmax + AV (3-term: Ph*Vh + Pl*Vh + Ph*Vl); plain bf16 ctx -------
// smem: e 4x4096 | Phi 4x2560 | Plo 4x2560 | Vh 4x5120 | Vl 4x5120 = 77824 B
#define AT_SMEM 77824

__global__ void __launch_bounds__(128) k_attn_mma() {
    extern __shared__ char smA[];
    const int tid = threadIdx.x, lane = tid & 31, w = tid >> 5;
    const int b = blockIdx.x >> 1;
    const int h = ((blockIdx.x & 1) << 2) + w;
    const uint32_t sbase = smem_u32(smA);
    char* e_t   = smA + w * 4096;
    char* phi_p = smA + 16384 + w * 2560;
    char* plo_p = smA + 26624 + w * 2560;
    char* vh_p  = smA + 36864 + w * 5120;
    char* vl_p  = smA + 57344 + w * 5120;
    const uint32_t phi = sbase + 16384 + w * 2560;
    const uint32_t plo = sbase + 26624 + w * 2560;
    const uint32_t vh  = sbase + 36864 + w * 5120;
    const uint32_t vl  = sbase + 57344 + w * 5120;

    for (int i = lane; i < 640; i += 32) {
        ((uint32_t*)phi_p)[i] = 0u;
        ((uint32_t*)plo_p)[i] = 0u;
    }
    for (int d = lane; d < 64; d += 32) {
        *(__nv_bfloat16*)(vh_p + d * 80 + 62) = __float2bfloat16(0.f);
        *(__nv_bfloat16*)(vl_p + d * 80 + 62) = __float2bfloat16(0.f);
    }

    const float* ep = g_energy + (size_t)(b * 8 + h) * NPOS;
    for (int p = lane; p < NPOS; p += 32) {
        float v = fmaf(ep[p], g_sc2[p], g_sh2[p]);
        int r = p / SS, cc = p - r * SS;
        ((float*)e_t)[r * 33 + cc] = v;
    }
    // V (fp32) -> transposed split bf16 tiles
    const float* vp = g_vf + (size_t)(b * SS) * 512 + h * 64;
    for (int i = lane; i < SS * 16; i += 32) {
        int s = i >> 4, d0 = (i & 15) << 2;
        float4 vv = *(const float4*)(vp + (size_t)s * 512 + d0);
        float arr[4] = {vv.x, vv.y, vv.z, vv.w};
#pragma unroll
        for (int j = 0; j < 4; j++) {
            __nv_bfloat16 hi = __float2bfloat16(arr[j]);
            __nv_bfloat16 lo = __float2bfloat16(arr[j] - __bfloat162float(hi));
            *(__nv_bfloat16*)(vh_p + (d0 + j) * 80 + s * 2) = hi;
            *(__nv_bfloat16*)(vl_p + (d0 + j) * 80 + s * 2) = lo;
        }
    }
    __syncwarp();

    if (lane < SS) {
        float* row = (float*)e_t + lane * 33;
        float mx = -1e30f;
#pragma unroll
        for (int cc = 0; cc < SS; cc++) mx = fmaxf(mx, row[cc]);
        float sum = 0.f;
#pragma unroll
        for (int cc = 0; cc < SS; cc++) {
            float t = __expf(row[cc] - mx);
            row[cc] = t; sum += t;
        }
        float inv = 1.0f / sum;
#pragma unroll
        for (int cc = 0; cc < SS; cc++) {
            float p = row[cc] * inv;
            __nv_bfloat16 hi = __float2bfloat16(p);
            __nv_bfloat16 lo = __float2bfloat16(p - __bfloat162float(hi));
            *(__nv_bfloat16*)(phi_p + lane * 80 + cc * 2) = hi;
            *(__nv_bfloat16*)(plo_p + lane * 80 + cc * 2) = lo;
        }
    }
    __syncwarp();

    float acc[2][8][4];
#pragma unroll
    for (int i = 0; i < 2; i++)
#pragma unroll
        for (int j = 0; j < 8; j++)
#pragma unroll
            for (int l = 0; l < 4; l++) acc[i][j][l] = 0.f;

    const int a_row = lane & 15;
    const int a_cb  = (lane >> 4) * 16;
    const int b_row = (lane & 7) + ((lane >> 4) & 1) * 8;
    const int b_cb  = ((lane >> 3) & 1) * 16;

#pragma unroll
    for (int ks = 0; ks < 2; ks++) {
        uint32_t pf[2][4], lf[2][4], bh[16], bl[16];
#pragma unroll
        for (int mi = 0; mi < 2; mi++) {
            ldsm_x4(pf[mi], phi + (mi * 16 + a_row) * 80 + ks * 32 + a_cb);
            ldsm_x4(lf[mi], plo + (mi * 16 + a_row) * 80 + ks * 32 + a_cb);
        }
#pragma unroll
        for (int nt = 0; nt < 4; nt++) {
            ldsm_x4(&bh[nt * 4], vh + (nt * 16 + b_row) * 80 + ks * 32 + b_cb);
            ldsm_x4(&bl[nt * 4], vl + (nt * 16 + b_row) * 80 + ks * 32 + b_cb);
        }
#pragma unroll
        for (int mi = 0; mi < 2; mi++)
#pragma unroll
            for (int nj = 0; nj < 8; nj++)
                mma16816(acc[mi][nj], pf[mi], &bh[nj * 2]);
#pragma unroll
        for (int mi = 0; mi < 2; mi++)
#pragma unroll
            for (int nj = 0; nj < 8; nj++)
                mma16816(acc[mi][nj], lf[mi], &bh[nj * 2]);
#pragma unroll
        for (int mi = 0; mi < 2; mi++)
#pragma unroll
            for (int nj = 0; nj < 8; nj++)
                mma16816(acc[mi][nj], pf[mi], &bl[nj * 2]);
    }

    const int r1 = lane >> 2, c0 = (lane & 3) * 2;
#pragma unroll
    for (int mi = 0; mi < 2; mi++) {
#pragma unroll
        for (int nj = 0; nj < 8; nj++) {
            const int d = nj * 8 + c0;
            const int colg = h * 64 + d;
            const int q1 = mi * 16 + r1;
            const int q2 = q1 + 8;
            *(__nv_bfloat162*)(g_ctxb + ((size_t)b * 31 + q1) * 512 + colg) =
                __floats2bfloat162_rn(acc[mi][nj][0], acc[mi][nj][1]);
            if (q2 < 31)
                *(__nv_bfloat162*)(g_ctxb + ((size_t)b * 31 + q2) * 512 + colg) =
                    __floats2bfloat162_rn(acc[mi][nj][2], acc[mi][nj][3]);
        }
    }
}

// ---------------- launch ----------------
extern "C" void kernel_launch(void* const* d_in, const int* in_sizes, int n_in,
                              void* d_out, int out_size) {
    const float* x     = (const float*)d_in[0];
    const float* nw    = (const float*)d_in[1];
    const float* nbias = (const float*)d_in[2];
    const float* Wq    = (const float*)d_in[3];
    const float* Wk    = (const float*)d_in[4];
    const float* Wv    = (const float*)d_in[5];
    const float* Wout  = (const float*)d_in[6];
    const float* b_out = (const float*)d_in[7];
    const float* pw    = (const float*)d_in[8];
    const float* pb    = (const float*)d_in[9];
    float* out = (float*)d_out;

    cudaFuncSetAttribute(k_gemm_1t<0>, cudaFuncAttributeMaxDynamicSharedMemorySize, 65536);
    cudaFuncSetAttribute(k_gemm_1t<1>, cudaFuncAttributeMaxDynamicSharedMemorySize, 65536);
    cudaFuncSetAttribute(k_gemm_v, cudaFuncAttributeMaxDynamicSharedMemorySize, 53248);
    cudaFuncSetAttribute(k_energy_mma, cudaFuncAttributeMaxDynamicSharedMemorySize, E_SMEM);
    cudaFuncSetAttribute(k_attn_mma, cudaFuncAttributeMaxDynamicSharedMemorySize, AT_SMEM);

    k_pre1<<<NPART + 512, 256>>>(x, Wq, Wk, Wv, Wout);            // #1
    k_pre2<<<4, 256>>>(nw, nbias);                                // #2
    k_split_x<<<M_TOT / 4, 256>>>(x);                             // #3
    k_gemm_1t<0><<<dim3(8, 992), 128, 65536>>>(nullptr, nullptr, nullptr);  // #4 <- ncu
    k_gemm_v<<<dim3(4, 992), 128, 53248>>>();                     // #5
    k_energy_mma<<<BB, 256, E_SMEM>>>();                          // #6
    k_bn2_fin<<<4, 256>>>(pw, pb);                                // #7
    k_attn_mma<<<BB * 2, 128, AT_SMEM>>>();                       // #8
    k_gemm_1t<1><<<dim3(4, 992), 128, 65536>>>(b_out, x, out);    // #9
}

// round 14
// speedup vs baseline: 2.1554x; 1.0327x over previous
#include <cuda_runtime.h>
#include <cuda_bf16.h>
#include <cstdint>

// Problem constants
#define BB 4096
#define SS 31
#define CC 512
#define HH 8
#define HD 64
#define M_TOT (BB*SS)        // 126976
#define NPOS (SS*SS)         // 961
#define BH (BB*HH)           // 32768
#define EPS 1e-5f
#define INV_SQRT_C 0.044194173824159216f   // 1/sqrt(512)
#define NPART 992            // BN1 partial blocks

// ---------------- scratch (static device memory; no allocations) ----------------
__device__ __align__(16) __nv_bfloat16 g_xb[(size_t)M_TOT * 512];    // BN(x), hi only
__device__ __align__(16) __nv_bfloat16 g_ctxb[(size_t)M_TOT * 512];  // ctx, plain bf16
// Weights packed: per row 16 chunks of [32 hi | 32 lo] bf16 (128 B/chunk).
__device__ __align__(16) __nv_bfloat16 g_wp[(size_t)1536 * 1024];
__device__ __align__(16) __nv_bfloat16 g_wop[(size_t)512 * 1024];

__device__ __align__(16) __nv_bfloat16 g_qb[(size_t)M_TOT * CC];
__device__ __align__(16) __nv_bfloat16 g_kb[(size_t)M_TOT * CC];
__device__ __align__(16) float g_vf[(size_t)M_TOT * CC];             // v in fp32
__device__ __align__(16) __nv_bfloat16 g_energy[(size_t)BH * NPOS];  // energy bf16

// BN1 two-phase partials (no atomics)
__device__ __align__(16) float g_psum[(size_t)NPART * CC];
__device__ __align__(16) float g_psq[(size_t)NPART * CC];
__device__ __align__(16) float g_scale[CC];
__device__ __align__(16) float g_shift[CC];
__device__ __align__(16) float g_p_sum[NPOS];
__device__ __align__(16) float g_p_sq[NPOS];
__device__ __align__(16) float g_sc2[NPOS];
__device__ __align__(16) float g_sh2[NPOS];

// ---------------- helpers ----------------
__device__ __forceinline__ uint32_t smem_u32(const void* p) {
    uint32_t a;
    asm("{ .reg .u64 t; cvta.to.shared.u64 t, %1; cvt.u32.u64 %0, t; }" : "=r"(a) : "l"(p));
    return a;
}
__device__ __forceinline__ void cp16(uint32_t dst, const void* src) {
    asm volatile("cp.async.cg.shared.global [%0], [%1], 16;" :: "r"(dst), "l"(src) : "memory");
}
__device__ __forceinline__ void cp_commit() {
    asm volatile("cp.async.commit_group;" ::: "memory");
}
__device__ __forceinline__ void cp_wait1() {
    asm volatile("cp.async.wait_group 1;" ::: "memory");
}
__device__ __forceinline__ void cp_wait0() {
    asm volatile("cp.async.wait_group 0;" ::: "memory");
}
__device__ __forceinline__ void ldsm_x4(uint32_t* r, uint32_t addr) {
    asm volatile("ldmatrix.sync.aligned.m8n8.x4.shared.b16 {%0,%1,%2,%3}, [%4];"
                 : "=r"(r[0]), "=r"(r[1]), "=r"(r[2]), "=r"(r[3]) : "r"(addr));
}
__device__ __forceinline__ void mma16816(float* c, const uint32_t* a, const uint32_t* b) {
    asm volatile(
        "mma.sync.aligned.m16n8k16.row.col.f32.bf16.bf16.f32 "
        "{%0,%1,%2,%3}, {%4,%5,%6,%7}, {%8,%9}, {%0,%1,%2,%3};"
        : "+f"(c[0]), "+f"(c[1]), "+f"(c[2]), "+f"(c[3])
        : "r"(a[0]), "r"(a[1]), "r"(a[2]), "r"(a[3]), "r"(b[0]), "r"(b[1]));
}
#define SWZ(off) ((off) ^ (((off) >> 3) & 0x70u))

// ---------------- launch #1: BN1 partial stats + weight split (packed) --------------
__global__ void __launch_bounds__(256) k_pre1(const float* __restrict__ x,
                                              const float* __restrict__ Wq,
                                              const float* __restrict__ Wk,
                                              const float* __restrict__ Wv,
                                              const float* __restrict__ Wo) {
    const int tid = threadIdx.x;
    const int blk = blockIdx.x;
    if (blk < NPART) {
        const size_t r0 = (size_t)blk * 128;
        const float* xp = x + r0 * CC;
        float s0 = 0.f, s1 = 0.f, q0 = 0.f, q1 = 0.f;
        for (int r = 0; r < 128; r++) {
            float v0 = xp[(size_t)r * CC + tid];
            float v1 = xp[(size_t)r * CC + tid + 256];
            s0 += v0; q0 += v0 * v0;
            s1 += v1; q1 += v1 * v1;
        }
        g_psum[(size_t)blk * CC + tid]       = s0;
        g_psq [(size_t)blk * CC + tid]       = q0;
        g_psum[(size_t)blk * CC + tid + 256] = s1;
        g_psq [(size_t)blk * CC + tid + 256] = q1;
    } else {
        int t = (blk - NPART) * 256 + tid;   // [0, 131072)
        int row = t >> 6;
        int oct = t & 63;
        int c = oct >> 2, pos = (oct & 3) << 3, k = oct << 3;
        const float* src;
        __nv_bfloat16* dst;
        if (row < 1536) {
            src = (row < 512) ? (Wq + (size_t)row * 512)
                : (row < 1024) ? (Wk + (size_t)(row - 512) * 512)
                               : (Wv + (size_t)(row - 1024) * 512);
            dst = g_wp + (((size_t)row * 16 + c) << 6) + pos;
        } else {
            int r2 = row - 1536;
            src = Wo + (size_t)r2 * 512;
            dst = g_wop + (((size_t)r2 * 16 + c) << 6) + pos;
        }
        float4 a = *(const float4*)(src + k);
        float4 b = *(const float4*)(src + k + 4);
        float v[8] = {a.x, a.y, a.z, a.w, b.x, b.y, b.z, b.w};
        __nv_bfloat16 hi[8], lo[8];
#pragma unroll
        for (int i = 0; i < 8; i++) {
            hi[i] = __float2bfloat16(v[i]);
            lo[i] = __float2bfloat16(v[i] - __bfloat162float(hi[i]));
        }
        *(uint4*)dst        = *(uint4*)hi;
        *(uint4*)(dst + 32) = *(uint4*)lo;
    }
}

// ---------------- launch #2: BN1 finalize + zero BN2 buffers ----------------
__global__ void __launch_bounds__(256) k_pre2(const float* __restrict__ nw,
                                              const float* __restrict__ nb) {
    const int gid = blockIdx.x * 256 + threadIdx.x;   // <<<4,256>>>
    if (gid < CC) {
        float s = 0.f, q = 0.f;
        for (int p = 0; p < NPART; p++) {
            s += g_psum[(size_t)p * CC + gid];
            q += g_psq [(size_t)p * CC + gid];
        }
        const float inv_n = 1.0f / (float)M_TOT;
        float mean = s * inv_n;
        float var  = q * inv_n - mean * mean;
        float rs   = rsqrtf(var + EPS);
        float sc   = rs * nw[gid];
        g_scale[gid] = sc;
        g_shift[gid] = nb[gid] - mean * sc;
    }
    if (gid < NPOS) { g_p_sum[gid] = 0.f; g_p_sq[gid] = 0.f; }
}

// ---------------- launch #3: xn = BN(x) -> plain bf16 ----------------
__global__ void __launch_bounds__(256) k_split_x(const float* __restrict__ x) {
    size_t t = (size_t)blockIdx.x * 256 + threadIdx.x;
    size_t m = t >> 6;
    int k = (int)(t & 63) * 8;
    const float* xp = x + m * 512 + k;
    float4 a  = *(const float4*)xp;
    float4 b  = *(const float4*)(xp + 4);
    float4 sA = *(const float4*)(g_scale + k);
    float4 sB = *(const float4*)(g_scale + k + 4);
    float4 hA = *(const float4*)(g_shift + k);
    float4 hB = *(const float4*)(g_shift + k + 4);
    __nv_bfloat16 hb[8];
    hb[0] = __float2bfloat16(fmaf(a.x, sA.x, hA.x));
    hb[1] = __float2bfloat16(fmaf(a.y, sA.y, hA.y));
    hb[2] = __float2bfloat16(fmaf(a.z, sA.z, hA.z));
    hb[3] = __float2bfloat16(fmaf(a.w, sA.w, hA.w));
    hb[4] = __float2bfloat16(fmaf(b.x, sB.x, hB.x));
    hb[5] = __float2bfloat16(fmaf(b.y, sB.y, hB.y));
    hb[6] = __float2bfloat16(fmaf(b.z, sB.z, hB.z));
    hb[7] = __float2bfloat16(fmaf(b.w, sB.w, hB.w));
    *(uint4*)(g_xb + m * 512 + k) = *(uint4*)hb;
}

// ---------------- 1-term GEMM: 3-stage pipeline, one sync per iter ----------------
// MODE 0: A = g_xb, B = g_wp rows [0,1024) -> q/k bf16
// MODE 1: A = g_ctxb, B = g_wop -> out = D + bias + resid (fp32)
template<int MODE>
__global__ void __launch_bounds__(128) k_gemm_1t(const float* __restrict__ bias,
                                                 const float* __restrict__ resid,
                                                 float* __restrict__ Dout) {
    extern __shared__ char sm[];  // 3 stages x (A 16KB + B 16KB) = 96KB
    const int tid = threadIdx.x, lane = tid & 31, w = tid >> 5;
    const int wm = w >> 1, wn = w & 1;
    const int m0 = blockIdx.y * 128, n0g = blockIdx.x * 128;
    const __nv_bfloat16* Asrc = (MODE == 0) ? g_xb : g_ctxb;
    const __nv_bfloat16* Bsrc = (MODE == 0) ? g_wp : g_wop;
    const uint32_t sbase = smem_u32(sm);

    float c[4][8][4];
#pragma unroll
    for (int i = 0; i < 4; i++)
#pragma unroll
        for (int j = 0; j < 8; j++)
#pragma unroll
            for (int l = 0; l < 4; l++) c[i][j][l] = 0.f;

    const int a_row = lane & 15;
    const int a_cb  = (lane >> 4) * 16;
    const int b_row = (lane & 7) + ((lane >> 4) & 1) * 8;
    const int b_cb  = ((lane >> 3) & 1) * 16;

    auto load_stage = [&](int st, int s) {
        uint32_t abase = sbase + st * 32768;
        uint32_t bbase = abase + 16384;
#pragma unroll
        for (int j = 0; j < 8; j++) {
            int u = j * 128 + tid, r = u >> 3, q8 = u & 7;
            cp16(abase + SWZ((uint32_t)(r * 128 + q8 * 16)),
                 Asrc + (size_t)(m0 + r) * 512 + 64 * s + q8 * 8);
        }
#pragma unroll
        for (int j = 0; j < 8; j++) {
            int u = j * 128 + tid, r = u >> 3, q8 = u & 7;
            cp16(bbase + SWZ((uint32_t)(r * 128 + q8 * 16)),
                 Bsrc + (((size_t)(n0g + r) * 16 + 2 * s + (q8 >> 2)) << 6) + (q8 & 3) * 8);
        }
        cp_commit();
    };

    load_stage(0, 0);
    load_stage(1, 1);

    int stg = 0;
    for (int it = 0; it < 8; it++) {
        if (it + 1 < 8) cp_wait1(); else cp_wait0();
        __syncthreads();

        const uint32_t abase = sbase + stg * 32768;
        const uint32_t bbase = abase + 16384;

#pragma unroll
        for (int ks = 0; ks < 4; ks++) {
            uint32_t ah[16], bh[16];
#pragma unroll
            for (int mi = 0; mi < 4; mi++)
                ldsm_x4(&ah[mi * 4],
                        abase + SWZ((uint32_t)((wm * 64 + mi * 16 + a_row) * 128 + ks * 32 + a_cb)));
#pragma unroll
            for (int nt = 0; nt < 4; nt++)
                ldsm_x4(&bh[nt * 4],
                        bbase + SWZ((uint32_t)((wn * 64 + nt * 16 + b_row) * 128 + ks * 32 + b_cb)));
#pragma unroll
            for (int mi = 0; mi < 4; mi++)
#pragma unroll
                for (int nj = 0; nj < 8; nj++)
                    mma16816(c[mi][nj], &ah[mi * 4], &bh[nj * 2]);
        }
        if (it + 2 < 8) load_stage((stg + 2) % 3, it + 2);
        stg = (stg + 1) % 3;
    }

    const int r1 = lane >> 2;
    const int c0 = (lane & 3) * 2;
#pragma unroll
    for (int mi = 0; mi < 4; mi++) {
        const int gr = m0 + wm * 64 + mi * 16;
#pragma unroll
        for (int nj = 0; nj < 8; nj++) {
            const int gc = n0g + wn * 64 + nj * 8 + c0;
            if (MODE == 0) {
                const int sel = gc >> 9;
                const int col = gc & 511;
                __nv_bfloat16* op = (sel == 0) ? g_qb : g_kb;
                *(__nv_bfloat162*)(op + (size_t)(gr + r1) * 512 + col) =
                    __floats2bfloat162_rn(c[mi][nj][0], c[mi][nj][1]);
                *(__nv_bfloat162*)(op + (size_t)(gr + r1 + 8) * 512 + col) =
                    __floats2bfloat162_rn(c[mi][nj][2], c[mi][nj][3]);
            } else {
                const int col = gc;
                const float b0 = bias[col], b1 = bias[col + 1];
                {
                    const size_t off = (size_t)(gr + r1) * 512 + col;
                    float2 rv = *(const float2*)(resid + off);
                    *(float2*)(Dout + off) =
                        make_float2(c[mi][nj][0] + b0 + rv.x, c[mi][nj][1] + b1 + rv.y);
                }
                {
                    const size_t off = (size_t)(gr + r1 + 8) * 512 + col;
                    float2 rv = *(const float2*)(resid + off);
                    *(float2*)(Dout + off) =
                        make_float2(c[mi][nj][2] + b0 + rv.x, c[mi][nj][3] + b1 + rv.y);
                }
            }
        }
    }
}

// ---------------- v GEMM: 2-term (Ah*Bh + Ah*Bl), 3-stage, v stored fp32 ----------
__global__ void __launch_bounds__(128) k_gemm_v() {
    extern __shared__ char sm[];  // 3 x (10240 + 16384) = 79872
    const int tid = threadIdx.x, lane = tid & 31, w = tid >> 5;
    const int wm = w >> 1, wn = w & 1;
    const int m0 = blockIdx.y * 128, nb = blockIdx.x * 128;
    const uint32_t sbase = smem_u32(sm);

    float c[4][8][4];
#pragma unroll
    for (int i = 0; i < 4; i++)
#pragma unroll
        for (int j = 0; j < 8; j++)
#pragma unroll
            for (int l = 0; l < 4; l++) c[i][j][l] = 0.f;

    const int a_row = lane & 15;
    const int a_cb  = (lane >> 4) * 16;
    const int b_row = (lane & 7) + ((lane >> 4) & 1) * 8;
    const int b_cb  = ((lane >> 3) & 1) * 16;

    auto load_stage = [&](int st, int ch) {
        uint32_t abase = sbase + st * 26624;
        uint32_t bbase = abase + 10240;
#pragma unroll
        for (int j = 0; j < 4; j++) {
            int u = j * 128 + tid, r = u >> 2, q8 = u & 3;
            cp16(abase + (uint32_t)(r * 80 + q8 * 16),
                 g_xb + (size_t)(m0 + r) * 512 + 32 * ch + q8 * 8);
        }
#pragma unroll
        for (int j = 0; j < 8; j++) {
            int u = j * 128 + tid, r = u >> 3, q8 = u & 7;
            cp16(bbase + SWZ((uint32_t)(r * 128 + q8 * 16)),
                 g_wp + (((size_t)(1024 + nb + r) * 16 + ch) << 6) + q8 * 8);
        }
        cp_commit();
    };

    load_stage(0, 0);
    load_stage(1, 1);

    int stg = 0;
    for (int it = 0; it < 16; it++) {
        if (it + 1 < 16) cp_wait1(); else cp_wait0();
        __syncthreads();

        const uint32_t abase = sbase + stg * 26624;
        const uint32_t bbase = abase + 10240;

#pragma unroll
        for (int ks = 0; ks < 2; ks++) {
            uint32_t ah[16], bh[16], bl[16];
#pragma unroll
            for (int mi = 0; mi < 4; mi++)
                ldsm_x4(&ah[mi * 4],
                        abase + (uint32_t)((wm * 64 + mi * 16 + a_row) * 80 + ks * 32 + a_cb));
#pragma unroll
            for (int nt = 0; nt < 4; nt++)
                ldsm_x4(&bh[nt * 4],
                        bbase + SWZ((uint32_t)((wn * 64 + nt * 16 + b_row) * 128 + ks * 32 + b_cb)));
#pragma unroll
            for (int mi = 0; mi < 4; mi++)
#pragma unroll
                for (int nj = 0; nj < 8; nj++)
                    mma16816(c[mi][nj], &ah[mi * 4], &bh[nj * 2]);
#pragma unroll
            for (int nt = 0; nt < 4; nt++)
                ldsm_x4(&bl[nt * 4],
                        bbase + SWZ((uint32_t)((wn * 64 + nt * 16 + b_row) * 128 + 64 + ks * 32 + b_cb)));
#pragma unroll
            for (int mi = 0; mi < 4; mi++)
#pragma unroll
                for (int nj = 0; nj < 8; nj++)
                    mma16816(c[mi][nj], &ah[mi * 4], &bl[nj * 2]);
        }
        if (it + 2 < 16) load_stage((stg + 2) % 3, it + 2);
        stg = (stg + 1) % 3;
    }

    const int r1 = lane >> 2;
    const int c0 = (lane & 3) * 2;
#pragma unroll
    for (int mi = 0; mi < 4; mi++) {
        const int gr = m0 + wm * 64 + mi * 16;
#pragma unroll
        for (int nj = 0; nj < 8; nj++) {
            const int col = nb + wn * 64 + nj * 8 + c0;
            *(float2*)(g_vf + (size_t)(gr + r1) * 512 + col) =
                make_float2(c[mi][nj][0], c[mi][nj][1]);
            *(float2*)(g_vf + (size_t)(gr + r1 + 8) * 512 + col) =
                make_float2(c[mi][nj][2], c[mi][nj][3]);
        }
    }
}

// ---------------- energy via bf16 MMA + fused BN2 partials; energy stored bf16 ------
#define ET_ROWB 144
#define ET_SZ  (32 * ET_ROWB)
#define E_SMEM (16 * ET_SZ)            // 73728 B

__global__ void __launch_bounds__(256) k_energy_mma() {
    extern __shared__ char sm[];
    const int tid = threadIdx.x, lane = tid & 31, w = tid >> 5;   // w = head
    const int b = blockIdx.x;
    const uint32_t sbase = smem_u32(sm);
    const uint32_t qt = sbase + w * ET_SZ;
    const uint32_t kt = sbase + 8 * ET_SZ + w * ET_SZ;

    const __nv_bfloat16* qsrc = g_qb + (size_t)(b * SS) * 512 + w * 64;
    const __nv_bfloat16* ksrc = g_kb + (size_t)(b * SS) * 512 + w * 64;
    for (int i = lane; i < 248; i += 32) {
        int row = i >> 3, q8 = i & 7;
        cp16(qt + row * ET_ROWB + q8 * 16, qsrc + (size_t)row * 512 + q8 * 8);
        cp16(kt + row * ET_ROWB + q8 * 16, ksrc + (size_t)row * 512 + q8 * 8);
    }
    cp_commit();
    cp_wait0();
    if (lane < 16) {
        uint32_t base = (lane < 8) ? qt : kt;
        int q8 = lane & 7;
        uint4 z = make_uint4(0u, 0u, 0u, 0u);
        *(uint4*)(sm + (base - sbase) + 31 * ET_ROWB + q8 * 16) = z;
    }
    __syncthreads();

    float c[2][4][4];
#pragma unroll
    for (int i = 0; i < 2; i++)
#pragma unroll
        for (int j = 0; j < 4; j++)
#pragma unroll
            for (int l = 0; l < 4; l++) c[i][j][l] = 0.f;

    const int a_row = lane & 15;
    const int a_cb  = (lane >> 4) * 16;
    const int b_row = (lane & 7) + ((lane >> 4) & 1) * 8;
    const int b_cb  = ((lane >> 3) & 1) * 16;

#pragma unroll
    for (int ks = 0; ks < 4; ks++) {
        uint32_t af[2][4], bf[8];
#pragma unroll
        for (int mi = 0; mi < 2; mi++)
            ldsm_x4(af[mi], qt + (mi * 16 + a_row) * ET_ROWB + ks * 32 + a_cb);
#pragma unroll
        for (int g = 0; g < 2; g++)
            ldsm_x4(&bf[g * 4], kt + (g * 16 + b_row) * ET_ROWB + ks * 32 + b_cb);
#pragma unroll
        for (int mi = 0; mi < 2; mi++)
#pragma unroll
            for (int nj = 0; nj < 4; nj++)
                mma16816(c[mi][nj], af[mi], &bf[nj * 2]);
    }
    __syncthreads();

    float* stage = (float*)sm;
    const int r0 = lane >> 2, c0 = (lane & 3) * 2;
#pragma unroll
    for (int mi = 0; mi < 2; mi++)
#pragma unroll
        for (int nj = 0; nj < 4; nj++) {
            int rr = mi * 16 + r0, cc = nj * 8 + c0;
            stage[w * 1024 + rr * 32 + cc]           = c[mi][nj][0];
            stage[w * 1024 + rr * 32 + cc + 1]       = c[mi][nj][1];
            stage[w * 1024 + (rr + 8) * 32 + cc]     = c[mi][nj][2];
            stage[w * 1024 + (rr + 8) * 32 + cc + 1] = c[mi][nj][3];
        }
    __syncthreads();

    __nv_bfloat16* ebase = g_energy + (size_t)(b * 8) * NPOS;
    for (int p = tid; p < NPOS; p += 256) {
        int r = p / SS, cph = p - r * SS;
        int idx = r * 32 + cph;
        float s = 0.f, q = 0.f;
#pragma unroll
        for (int h = 0; h < 8; h++) {
            float v = stage[h * 1024 + idx];
            ebase[(size_t)h * NPOS + p] = __float2bfloat16(v);
            s += v; q += v * v;
        }
        atomicAdd(&g_p_sum[p], s);
        atomicAdd(&g_p_sq[p],  q);
    }
}

// ---------------- BN2 finalize ----------------
__global__ void k_bn2_fin(const float* __restrict__ pw, const float* __restrict__ pb) {
    int i = blockIdx.x * blockDim.x + threadIdx.x;
    if (i >= NPOS) return;
    float inv_n = 1.0f / (float)BH;
    float mean = g_p_sum[i] * inv_n;
    float var  = g_p_sq[i] * inv_n - mean * mean;
    float rs   = rsqrtf(var + EPS);
    float a    = rs * pw[i] * INV_SQRT_C;
    g_sc2[i] = a;
    g_sh2[i] = pb[i] * INV_SQRT_C - mean * a;
}

// ---------------- softmax + AV (3-term); plain bf16 ctx ----------------
#define AT_SMEM 77824

__global__ void __launch_bounds__(128) k_attn_mma() {
    extern __shared__ char smA[];
    const int tid = threadIdx.x, lane = tid & 31, w = tid >> 5;
    const int b = blockIdx.x >> 1;
    const int h = ((blockIdx.x & 1) << 2) + w;
    const uint32_t sbase = smem_u32(smA);
    char* e_t   = smA + w * 4096;
    char* phi_p = smA + 16384 + w * 2560;
    char* plo_p = smA + 26624 + w * 2560;
    char* vh_p  = smA + 36864 + w * 5120;
    char* vl_p  = smA + 57344 + w * 5120;
    const uint32_t phi = sbase + 16384 + w * 2560;
    const uint32_t plo = sbase + 26624 + w * 2560;
    const uint32_t vh  = sbase + 36864 + w * 5120;
    const uint32_t vl  = sbase + 57344 + w * 5120;

    for (int i = lane; i < 640; i += 32) {
        ((uint32_t*)phi_p)[i] = 0u;
        ((uint32_t*)plo_p)[i] = 0u;
    }
    for (int d = lane; d < 64; d += 32) {
        *(__nv_bfloat16*)(vh_p + d * 80 + 62) = __float2bfloat16(0.f);
        *(__nv_bfloat16*)(vl_p + d * 80 + 62) = __float2bfloat16(0.f);
    }

    const __nv_bfloat16* ep = g_energy + (size_t)(b * 8 + h) * NPOS;
    for (int p = lane; p < NPOS; p += 32) {
        float v = fmaf(__bfloat162float(ep[p]), g_sc2[p], g_sh2[p]);
        int r = p / SS, cc = p - r * SS;
        ((float*)e_t)[r * 33 + cc] = v;
    }
    const float* vp = g_vf + (size_t)(b * SS) * 512 + h * 64;
    for (int i = lane; i < SS * 16; i += 32) {
        int s = i >> 4, d0 = (i & 15) << 2;
        float4 vv = *(const float4*)(vp + (size_t)s * 512 + d0);
        float arr[4] = {vv.x, vv.y, vv.z, vv.w};
#pragma unroll
        for (int j = 0; j < 4; j++) {
            __nv_bfloat16 hi = __float2bfloat16(arr[j]);
            __nv_bfloat16 lo = __float2bfloat16(arr[j] - __bfloat162float(hi));
            *(__nv_bfloat16*)(vh_p + (d0 + j) * 80 + s * 2) = hi;
            *(__nv_bfloat16*)(vl_p + (d0 + j) * 80 + s * 2) = lo;
        }
    }
    __syncwarp();

    if (lane < SS) {
        float* row = (float*)e_t + lane * 33;
        float mx = -1e30f;
#pragma unroll
        for (int cc = 0; cc < SS; cc++) mx = fmaxf(mx, row[cc]);
        float sum = 0.f;
#pragma unroll
        for (int cc = 0; cc < SS; cc++) {
            float t = __expf(row[cc] - mx);
            row[cc] = t; sum += t;
        }
        float inv = 1.0f / sum;
#pragma unroll
        for (int cc = 0; cc < SS; cc++) {
            float p = row[cc] * inv;
            __nv_bfloat16 hi = __float2bfloat16(p);
            __nv_bfloat16 lo = __float2bfloat16(p - __bfloat162float(hi));
            *(__nv_bfloat16*)(phi_p + lane * 80 + cc * 2) = hi;
            *(__nv_bfloat16*)(plo_p + lane * 80 + cc * 2) = lo;
        }
    }
    __syncwarp();

    float acc[2][8][4];
#pragma unroll
    for (int i = 0; i < 2; i++)
#pragma unroll
        for (int j = 0; j < 8; j++)
#pragma unroll
            for (int l = 0; l < 4; l++) acc[i][j][l] = 0.f;

    const int a_row = lane & 15;
    const int a_cb  = (lane >> 4) * 16;
    const int b_row = (lane & 7) + ((lane >> 4) & 1) * 8;
    const int b_cb  = ((lane >> 3) & 1) * 16;

#pragma unroll
    for (int ks = 0; ks < 2; ks++) {
        uint32_t pf[2][4], lf[2][4], bh[16], bl[16];
#pragma unroll
        for (int mi = 0; mi < 2; mi++) {
            ldsm_x4(pf[mi], phi + (mi * 16 + a_row) * 80 + ks * 32 + a_cb);
            ldsm_x4(lf[mi], plo + (mi * 16 + a_row) * 80 + ks * 32 + a_cb);
        }
#pragma unroll
        for (int nt = 0; nt < 4; nt++) {
            ldsm_x4(&bh[nt * 4], vh + (nt * 16 + b_row) * 80 + ks * 32 + b_cb);
            ldsm_x4(&bl[nt * 4], vl + (nt * 16 + b_row) * 80 + ks * 32 + b_cb);
        }
#pragma unroll
        for (int mi = 0; mi < 2; mi++)
#pragma unroll
            for (int nj = 0; nj < 8; nj++)
                mma16816(acc[mi][nj], pf[mi], &bh[nj * 2]);
#pragma unroll
        for (int mi = 0; mi < 2; mi++)
#pragma unroll
            for (int nj = 0; nj < 8; nj++)
                mma16816(acc[mi][nj], lf[mi], &bh[nj * 2]);
#pragma unroll
        for (int mi = 0; mi < 2; mi++)
#pragma unroll
            for (int nj = 0; nj < 8; nj++)
                mma16816(acc[mi][nj], pf[mi], &bl[nj * 2]);
    }

    const int r1 = lane >> 2, c0 = (lane & 3) * 2;
#pragma unroll
    for (int mi = 0; mi < 2; mi++) {
#pragma unroll
        for (int nj = 0; nj < 8; nj++) {
            const int d = nj * 8 + c0;
            const int colg = h * 64 + d;
            const int q1 = mi * 16 + r1;
            const int q2 = q1 + 8;
            *(__nv_bfloat162*)(g_ctxb + ((size_t)b * 31 + q1) * 512 + colg) =
                __floats2bfloat162_rn(acc[mi][nj][0], acc[mi][nj][1]);
            if (q2 < 31)
                *(__nv_bfloat162*)(g_ctxb + ((size_t)b * 31 + q2) * 512 + colg) =
                    __floats2bfloat162_rn(acc[mi][nj][2], acc[mi][nj][3]);
        }
    }
}

// ---------------- launch ----------------
extern "C" void kernel_launch(void* const* d_in, const int* in_sizes, int n_in,
                              void* d_out, int out_size) {
    const float* x     = (const float*)d_in[0];
    const float* nw    = (const float*)d_in[1];
    const float* nbias = (const float*)d_in[2];
    const float* Wq    = (const float*)d_in[3];
    const float* Wk    = (const float*)d_in[4];
    const float* Wv    = (const float*)d_in[5];
    const float* Wout  = (const float*)d_in[6];
    const float* b_out = (const float*)d_in[7];
    const float* pw    = (const float*)d_in[8];
    const float* pb    = (const float*)d_in[9];
    float* out = (float*)d_out;

    cudaFuncSetAttribute(k_gemm_1t<0>, cudaFuncAttributeMaxDynamicSharedMemorySize, 98304);
    cudaFuncSetAttribute(k_gemm_1t<1>, cudaFuncAttributeMaxDynamicSharedMemorySize, 98304);
    cudaFuncSetAttribute(k_gemm_v, cudaFuncAttributeMaxDynamicSharedMemorySize, 79872);
    cudaFuncSetAttribute(k_energy_mma, cudaFuncAttributeMaxDynamicSharedMemorySize, E_SMEM);
    cudaFuncSetAttribute(k_attn_mma, cudaFuncAttributeMaxDynamicSharedMemorySize, AT_SMEM);

    k_pre1<<<NPART + 512, 256>>>(x, Wq, Wk, Wv, Wout);            // #1
    k_pre2<<<4, 256>>>(nw, nbias);                                // #2
    k_split_x<<<M_TOT / 4, 256>>>(x);                             // #3
    k_gemm_1t<0><<<dim3(8, 992), 128, 98304>>>(nullptr, nullptr, nullptr);  // #4 <- ncu
    k_gemm_v<<<dim3(4, 992), 128, 79872>>>();                     // #5
    k_energy_mma<<<BB, 256, E_SMEM>>>();                          // #6
    k_bn2_fin<<<4, 256>>>(pw, pb);                                // #7
    k_attn_mma<<<BB * 2, 128, AT_SMEM>>>();                       // #8
    k_gemm_1t<1><<<dim3(4, 992), 128, 98304>>>(b_out, x, out);    // #9
}